// round 10
// baseline (speedup 1.0000x reference)
#include <cuda_runtime.h>
#include <math.h>

#define TLEN    2048
#define HEADS_N 8
#define BATCH   2
#define SDIM    64
#define EDIM    512
#define QE_BH   2162688   // 4096 * 528 floats per (b,h)

// ---------------- scratch + resolved input pointers (device-resident) ----------
__device__ float g_q[BATCH*HEADS_N*TLEN*SDIM];
__device__ float g_k[BATCH*HEADS_N*TLEN*SDIM];
__device__ float g_v[BATCH*HEADS_N*TLEN*SDIM];
__device__ float g_vmean[BATCH*HEADS_N*SDIM];
__device__ float g_vpart[8][BATCH*HEADS_N][SDIM];
__device__ float g_attn[BATCH*TLEN*EDIM];
__device__ float g_qe[BATCH*HEADS_N*QE_BH];   // triangular-packed QE bands

__device__ const float*        g_pWq;
__device__ const float*        g_pWk;
__device__ const float*        g_pWv;
__device__ const unsigned int* g_pmask;

// ---------------- tf32 helpers ----------------
__device__ __forceinline__ unsigned int f2tf32(float x) {
    unsigned int r;
    asm("cvt.rna.tf32.f32 %0, %1;" : "=r"(r) : "f"(x));
    return r;
}
__device__ __forceinline__ void mma_tf32(float d[4],
        unsigned int a0, unsigned int a1, unsigned int a2, unsigned int a3,
        unsigned int b0, unsigned int b1) {
    asm("mma.sync.aligned.m16n8k8.row.col.f32.tf32.tf32.f32 "
        "{%0,%1,%2,%3}, {%4,%5,%6,%7}, {%8,%9}, {%0,%1,%2,%3};"
        : "+f"(d[0]), "+f"(d[1]), "+f"(d[2]), "+f"(d[3])
        : "r"(a0), "r"(a1), "r"(a2), "r"(a3), "r"(b0), "r"(b1));
}

// ---------------- prologue: content-based identification of mask ---------------
__global__ void select_inputs(const float* c0, const float* c1,
                              const float* c2, const float* c3, int x_first) {
    __shared__ int bad[4];
    const float* cand[4] = {c0, c1, c2, c3};
    if (threadIdx.x < 4) bad[threadIdx.x] = 0;
    __syncthreads();
    for (int j = 0; j < 4; j++) {
        const unsigned int* p = (const unsigned int*)cand[j];
        int b = 0;
        for (int i = threadIdx.x; i < SDIM*SDIM; i += blockDim.x) {
            unsigned int v = p[i];
            if (v != 0u && v != 1u && v != 0x3F800000u) { b = 1; break; }
        }
        if (b) atomicOr(&bad[j], 1);
    }
    __syncthreads();
    if (threadIdx.x == 0) {
        int mi = -1;
        for (int j = 0; j < 4; j++) if (!bad[j]) { mi = j; break; }
        if (mi < 0) mi = x_first ? 0 : 3;
        const float* rest[3]; int n = 0;
        for (int j = 0; j < 4; j++) if (j != mi) rest[n++] = cand[j];
        g_pmask = (const unsigned int*)cand[mi];
        if (x_first) { g_pWq = rest[0]; g_pWk = rest[1]; g_pWv = rest[2]; }
        else         { g_pWk = rest[0]; g_pWq = rest[1]; g_pWv = rest[2]; }
    }
}

// ---------------- QKV projection (swizzled float4 smem) ----------------
__global__ void proj_kernel(const float* __restrict__ x) {
    extern __shared__ float sm[];
    float* sW = sm;              // 192 rows x 64, swizzled
    float* sX = sm + 192*64;     // 128 rows x 64, swizzled
    const int t0 = blockIdx.x * 128;
    const int h  = blockIdx.y;
    const int b  = blockIdx.z;
    const int tid = threadIdx.x;
    const float* W[3] = {g_pWq, g_pWk, g_pWv};

    for (int k = tid; k < 3*64*16; k += 256) {
        int row = k >> 4, i4 = k & 15;
        int mm = row >> 6, o = row & 63;
        float4 f = *(const float4*)&W[mm][o*SDIM + i4*4];
        *(float4*)&sW[row*64 + ((i4 ^ o) & 15)*4] = f;
    }
    for (int k = tid; k < 128*16; k += 256) {
        int row = k >> 4, i4 = k & 15;
        float4 f = *(const float4*)&x[(size_t)(b*TLEN + t0 + row)*EDIM + h*SDIM + i4*4];
        *(float4*)&sX[row*64 + ((i4 ^ (row & 15)) & 15)*4] = f;
    }
    __syncthreads();

    for (int idx = tid; idx < 128*192; idx += 256) {
        int row = idx / 192;
        int rem = idx - row*192;
        float a = 0.f;
        const int mw = rem & 15;
        const int mx = row & 15;
        #pragma unroll
        for (int i4 = 0; i4 < 16; i4++) {
            float4 w4 = *(const float4*)&sW[rem*64 + ((i4 ^ mw) & 15)*4];
            float4 x4 = *(const float4*)&sX[row*64 + ((i4 ^ mx) & 15)*4];
            a = fmaf(w4.x, x4.x, a); a = fmaf(w4.y, x4.y, a);
            a = fmaf(w4.z, x4.z, a); a = fmaf(w4.w, x4.w, a);
        }
        int mm = rem >> 6, o = rem & 63;
        float* dst = (mm == 0) ? g_q : (mm == 1) ? g_k : g_v;
        dst[((size_t)(b*HEADS_N + h)*TLEN + t0 + row)*SDIM + o] = a;
    }
}

// ---------------- rel-pos GEMM: QE[i_l][o] = q_{i0+i_l} . Er[h][T-64-i0+o] ------
__global__ void __launch_bounds__(256) relgemm_kernel(const float* __restrict__ Er) {
    extern __shared__ float sm[];
    float* Qh = sm;              // [m=64][k] stride 68
    float* Ql = Qh + 64*68;
    float* Eh = Ql + 64*68;      // [k=64][n=o] stride 68
    float* El = Eh + 64*68;

    const int x = blockIdx.x;
    const int h = blockIdx.y, b = blockIdx.z;
    int it = (int)((sqrtf(8.f*(float)x + 1.f) - 1.f) * 0.5f);
    while ((it + 1)*(it + 2)/2 <= x) it++;
    while (it*(it + 1)/2 > x) it--;
    const int oc = x - it*(it + 1)/2;          // 0..it
    const int i0 = it * 64;
    const int j0 = TLEN - 64 - i0 + oc*64;     // Er row base (>= 0)

    const int tid = threadIdx.x;
    const float* gq = g_q + (size_t)(b*HEADS_N + h)*TLEN*SDIM + (size_t)i0*SDIM;
    const float* ge = Er + (size_t)h*TLEN*SDIM;

    #pragma unroll
    for (int kk = 0; kk < 4; kk++) {
        int k = kk*256 + tid;
        int m = k >> 4, s4 = (k & 15)*4;
        float4 f = *(const float4*)&gq[m*SDIM + s4];
        float hx = __uint_as_float(f2tf32(f.x));
        float hy = __uint_as_float(f2tf32(f.y));
        float hz = __uint_as_float(f2tf32(f.z));
        float hw = __uint_as_float(f2tf32(f.w));
        *(float4*)&Qh[m*68 + s4] = make_float4(hx, hy, hz, hw);
        *(float4*)&Ql[m*68 + s4] = make_float4(
            __uint_as_float(f2tf32(f.x - hx)), __uint_as_float(f2tf32(f.y - hy)),
            __uint_as_float(f2tf32(f.z - hz)), __uint_as_float(f2tf32(f.w - hw)));
    }
    #pragma unroll
    for (int kk = 0; kk < 4; kk++) {
        int k = kk*256 + tid;
        int s4 = (k >> 6)*4, o = k & 63;
        float4 f = *(const float4*)&ge[(size_t)(j0 + o)*SDIM + s4];
        float hv[4], lv[4];
        float fv[4] = {f.x, f.y, f.z, f.w};
        #pragma unroll
        for (int i = 0; i < 4; i++) {
            hv[i] = __uint_as_float(f2tf32(fv[i]));
            lv[i] = __uint_as_float(f2tf32(fv[i] - hv[i]));
        }
        #pragma unroll
        for (int i = 0; i < 4; i++) {
            Eh[(s4 + i)*68 + o] = hv[i];
            El[(s4 + i)*68 + o] = lv[i];
        }
    }
    __syncthreads();

    const int w = tid >> 5, lane = tid & 31;
    const int g = lane >> 2, tg = lane & 3;
    const int mr = (w & 3)*16 + g;
    const int nb = (w >> 2)*32;

    float d[4][4];
    #pragma unroll
    for (int nt = 0; nt < 4; nt++)
        #pragma unroll
        for (int i = 0; i < 4; i++) d[nt][i] = 0.f;

    #pragma unroll
    for (int kk = 0; kk < 8; kk++) {
        const int k0 = kk*8;
        unsigned int ah0 = __float_as_uint(Qh[mr*68 + k0 + tg]);
        unsigned int ah1 = __float_as_uint(Qh[(mr + 8)*68 + k0 + tg]);
        unsigned int ah2 = __float_as_uint(Qh[mr*68 + k0 + tg + 4]);
        unsigned int ah3 = __float_as_uint(Qh[(mr + 8)*68 + k0 + tg + 4]);
        unsigned int al0 = __float_as_uint(Ql[mr*68 + k0 + tg]);
        unsigned int al1 = __float_as_uint(Ql[(mr + 8)*68 + k0 + tg]);
        unsigned int al2 = __float_as_uint(Ql[mr*68 + k0 + tg + 4]);
        unsigned int al3 = __float_as_uint(Ql[(mr + 8)*68 + k0 + tg + 4]);
        #pragma unroll
        for (int nt = 0; nt < 4; nt++) {
            const int n = nb + nt*8 + g;
            unsigned int bh0 = __float_as_uint(Eh[(k0 + tg)*68 + n]);
            unsigned int bh1 = __float_as_uint(Eh[(k0 + tg + 4)*68 + n]);
            unsigned int bl0 = __float_as_uint(El[(k0 + tg)*68 + n]);
            unsigned int bl1 = __float_as_uint(El[(k0 + tg + 4)*68 + n]);
            mma_tf32(d[nt], ah0, ah1, ah2, ah3, bh0, bh1);
            mma_tf32(d[nt], ah0, ah1, ah2, ah3, bl0, bl1);
            mma_tf32(d[nt], al0, al1, al2, al3, bh0, bh1);
        }
    }

    const int W = 64*(it + 1);
    float* qb = g_qe + (size_t)(b*HEADS_N + h)*QE_BH + (size_t)4096*(it*(it + 1)/2);
    const int colb = oc*64 + nb;
    #pragma unroll
    for (int nt = 0; nt < 4; nt++) {
        const int col = colb + nt*8 + 2*tg;
        *(float2*)&qb[(size_t)mr*W + col]       = make_float2(d[nt][0], d[nt][1]);
        *(float2*)&qb[(size_t)(mr + 8)*W + col] = make_float2(d[nt][2], d[nt][3]);
    }
}

// ---------------- V mean, two-stage (deterministic, full-chip) ----------------
__global__ void vmean1_kernel() {
    const int bh = blockIdx.x, ch = blockIdx.y;
    const int tid = threadIdx.x;
    const int d = tid & 63, sub = tid >> 6;
    __shared__ float red[4][64];
    float a = 0.f;
    for (int l = ch*256 + sub; l < (ch + 1)*256; l += 4)
        a += g_v[((size_t)bh*TLEN + l)*SDIM + d];
    red[sub][d] = a;
    __syncthreads();
    if (sub == 0)
        g_vpart[ch][bh][d] = red[0][d] + red[1][d] + red[2][d] + red[3][d];
}
__global__ void vmean2_kernel() {
    const int bh = blockIdx.x, d = threadIdx.x;
    float a = 0.f;
    #pragma unroll
    for (int c = 0; c < 8; c++) a += g_vpart[c][bh][d];
    g_vmean[bh*SDIM + d] = a * (1.f/(float)TLEN);
}

// ---------------- tensor-core flash attention (QK + QE band + PV) --------------
// grid: (TLEN/64 reversed, H, B), 128 threads = 4 warps; warp w owns S rows
// [w*16, w*16+16). All operands pre-converted to tf32 hi/lo in smem; inner
// loops are pure LDS + mma (3x tf32 split = fp32-grade accuracy).
// AST=68: 68 mod 32 == 4 -> fragment loads are bank-conflict-free.
#define AST 68
__global__ void __launch_bounds__(128, 2) attn_kernel() {
    extern __shared__ float sm[];
    float* sQh = sm;               // [i][s]  64 x AST
    float* sQl = sQh + 64*AST;
    float* sKh = sQl + 64*AST;     // [c][s]  (pre-scaled); aliased by Ph after S-GEMM
    float* sKl = sKh + 64*AST;     //          aliased by Pl
    float* sVh = sKl + 64*AST;     // [lc][d]
    float* sVl = sVh + 64*AST;
    float* sPh = sKh;              // [i][lc]
    float* sPl = sKl;

    const int rbx = (int)gridDim.x - 1 - (int)blockIdx.x;   // heavy tiles first
    const int i0 = rbx * 64;
    const int h  = blockIdx.y;
    const int b  = blockIdx.z;
    const int tid = threadIdx.x;
    const int w = tid >> 5, lane = tid & 31;
    const int g = lane >> 2, tg = lane & 3;
    const int rA = w*16 + g, rB = rA + 8;
    const float scale2 = 0.04419417382415922f;   // 512^-0.5

    const size_t bh = (size_t)(b*HEADS_N + h);
    const float* gq = g_q + bh*TLEN*SDIM;
    const float* gk = g_k + bh*TLEN*SDIM;
    const float* gv = g_v + bh*TLEN*SDIM;

    const int it = i0 >> 6;
    const int Wqe = 64*(it + 1);
    const float* qeb = g_qe + bh*QE_BH + (size_t)4096*(it*(it + 1)/2);
    const int omax = i0 + 63;

    // stage Q hi/lo once
    for (int k = tid; k < 1024; k += 128) {
        int li = k >> 4, s4 = (k & 15)*4;
        float4 f = *(const float4*)&gq[(size_t)(i0 + li)*SDIM + s4];
        float hx = __uint_as_float(f2tf32(f.x));
        float hy = __uint_as_float(f2tf32(f.y));
        float hz = __uint_as_float(f2tf32(f.z));
        float hw = __uint_as_float(f2tf32(f.w));
        *(float4*)&sQh[li*AST + s4] = make_float4(hx, hy, hz, hw);
        *(float4*)&sQl[li*AST + s4] = make_float4(
            __uint_as_float(f2tf32(f.x - hx)), __uint_as_float(f2tf32(f.y - hy)),
            __uint_as_float(f2tf32(f.z - hz)), __uint_as_float(f2tf32(f.w - hw)));
    }

    float mA = -1e30f, mB = -1e30f, lA = 0.f, lB = 0.f;
    float O[8][4];
    #pragma unroll
    for (int nt = 0; nt < 8; nt++)
        #pragma unroll
        for (int i = 0; i < 4; i++) O[nt][i] = 0.f;

    for (int ct = 0; ct <= it; ct++) {
        const int c0 = ct * 64;
        __syncthreads();   // prev iter fully consumed (covers Q staging too)

        // stage K hi/lo (pre-scaled) and V hi/lo
        for (int k = tid; k < 1024; k += 128) {
            int li = k >> 4, s4 = (k & 15)*4;
            float4 f = *(const float4*)&gk[(size_t)(c0 + li)*SDIM + s4];
            f.x *= scale2; f.y *= scale2; f.z *= scale2; f.w *= scale2;
            float khx = __uint_as_float(f2tf32(f.x));
            float khy = __uint_as_float(f2tf32(f.y));
            float khz = __uint_as_float(f2tf32(f.z));
            float khw = __uint_as_float(f2tf32(f.w));
            *(float4*)&sKh[li*AST + s4] = make_float4(khx, khy, khz, khw);
            *(float4*)&sKl[li*AST + s4] = make_float4(
                __uint_as_float(f2tf32(f.x - khx)), __uint_as_float(f2tf32(f.y - khy)),
                __uint_as_float(f2tf32(f.z - khz)), __uint_as_float(f2tf32(f.w - khw)));
            float4 v = *(const float4*)&gv[(size_t)(c0 + li)*SDIM + s4];
            float vhx = __uint_as_float(f2tf32(v.x));
            float vhy = __uint_as_float(f2tf32(v.y));
            float vhz = __uint_as_float(f2tf32(v.z));
            float vhw = __uint_as_float(f2tf32(v.w));
            *(float4*)&sVh[li*AST + s4] = make_float4(vhx, vhy, vhz, vhw);
            *(float4*)&sVl[li*AST + s4] = make_float4(
                __uint_as_float(f2tf32(v.x - vhx)), __uint_as_float(f2tf32(v.y - vhy)),
                __uint_as_float(f2tf32(v.z - vhz)), __uint_as_float(f2tf32(v.w - vhw)));
        }
        __syncthreads();

        // ---- S = Q K^T (pure LDS + mma) ----
        float acc[8][4];
        #pragma unroll
        for (int nt = 0; nt < 8; nt++)
            #pragma unroll
            for (int i = 0; i < 4; i++) acc[nt][i] = 0.f;

        #pragma unroll
        for (int kk = 0; kk < 8; kk++) {
            const int k0 = kk*8;
            unsigned int ah0 = __float_as_uint(sQh[rA*AST + k0 + tg]);
            unsigned int ah1 = __float_as_uint(sQh[rB*AST + k0 + tg]);
            unsigned int ah2 = __float_as_uint(sQh[rA*AST + k0 + tg + 4]);
            unsigned int ah3 = __float_as_uint(sQh[rB*AST + k0 + tg + 4]);
            unsigned int al0 = __float_as_uint(sQl[rA*AST + k0 + tg]);
            unsigned int al1 = __float_as_uint(sQl[rB*AST + k0 + tg]);
            unsigned int al2 = __float_as_uint(sQl[rA*AST + k0 + tg + 4]);
            unsigned int al3 = __float_as_uint(sQl[rB*AST + k0 + tg + 4]);
            #pragma unroll
            for (int nt = 0; nt < 8; nt++) {
                const int n = nt*8 + g;
                unsigned int bh0 = __float_as_uint(sKh[n*AST + k0 + tg]);
                unsigned int bh1 = __float_as_uint(sKh[n*AST + k0 + tg + 4]);
                unsigned int bl0 = __float_as_uint(sKl[n*AST + k0 + tg]);
                unsigned int bl1 = __float_as_uint(sKl[n*AST + k0 + tg + 4]);
                mma_tf32(acc[nt], ah0, ah1, ah2, ah3, bh0, bh1);
                mma_tf32(acc[nt], ah0, ah1, ah2, ah3, bl0, bl1);
                mma_tf32(acc[nt], al0, al1, al2, al3, bh0, bh1);
            }
        }

        // ---- add precomputed rel-pos band + causal mask ----
        #pragma unroll
        for (int nt = 0; nt < 8; nt++) {
            const int cl = nt*8 + 2*tg;
            const int oA = 63 - rA + c0 + cl;
            const int oB = 63 - rB + c0 + cl;
            if (oA     <= omax) acc[nt][0] += __ldg(qeb + (size_t)rA*Wqe + oA);
            if (oA + 1 <= omax) acc[nt][1] += __ldg(qeb + (size_t)rA*Wqe + oA + 1);
            if (oB     <= omax) acc[nt][2] += __ldg(qeb + (size_t)rB*Wqe + oB);
            if (oB + 1 <= omax) acc[nt][3] += __ldg(qeb + (size_t)rB*Wqe + oB + 1);
            if (ct == it) {
                if (cl     > rA) acc[nt][0] = -1e30f;
                if (cl + 1 > rA) acc[nt][1] = -1e30f;
                if (cl     > rB) acc[nt][2] = -1e30f;
                if (cl + 1 > rB) acc[nt][3] = -1e30f;
            }
        }

        // ---- online softmax (rows rA, rB; quad = lanes sharing g) ----
        float mxA = -1e30f, mxB = -1e30f;
        #pragma unroll
        for (int nt = 0; nt < 8; nt++) {
            mxA = fmaxf(mxA, fmaxf(acc[nt][0], acc[nt][1]));
            mxB = fmaxf(mxB, fmaxf(acc[nt][2], acc[nt][3]));
        }
        mxA = fmaxf(mxA, __shfl_xor_sync(0xffffffffu, mxA, 1));
        mxA = fmaxf(mxA, __shfl_xor_sync(0xffffffffu, mxA, 2));
        mxB = fmaxf(mxB, __shfl_xor_sync(0xffffffffu, mxB, 1));
        mxB = fmaxf(mxB, __shfl_xor_sync(0xffffffffu, mxB, 2));
        const float mnA = fmaxf(mA, mxA), mnB = fmaxf(mB, mxB);
        const float cA = __expf(mA - mnA), cB = __expf(mB - mnB);
        float sA = 0.f, sB = 0.f;
        #pragma unroll
        for (int nt = 0; nt < 8; nt++) {
            acc[nt][0] = __expf(acc[nt][0] - mnA);
            acc[nt][1] = __expf(acc[nt][1] - mnA);
            acc[nt][2] = __expf(acc[nt][2] - mnB);
            acc[nt][3] = __expf(acc[nt][3] - mnB);
            sA += acc[nt][0] + acc[nt][1];
            sB += acc[nt][2] + acc[nt][3];
        }
        sA += __shfl_xor_sync(0xffffffffu, sA, 1);
        sA += __shfl_xor_sync(0xffffffffu, sA, 2);
        sB += __shfl_xor_sync(0xffffffffu, sB, 1);
        sB += __shfl_xor_sync(0xffffffffu, sB, 2);
        lA = lA*cA + sA;  mA = mnA;
        lB = lB*cB + sB;  mB = mnB;
        #pragma unroll
        for (int nt = 0; nt < 8; nt++) {
            O[nt][0] *= cA; O[nt][1] *= cA;
            O[nt][2] *= cB; O[nt][3] *= cB;
        }

        // ---- P -> smem hi/lo (aliases K tiles; all warps must be done with K) --
        __syncthreads();
        #pragma unroll
        for (int nt = 0; nt < 8; nt++) {
            float h0 = __uint_as_float(f2tf32(acc[nt][0]));
            float h1 = __uint_as_float(f2tf32(acc[nt][1]));
            float h2 = __uint_as_float(f2tf32(acc[nt][2]));
            float h3 = __uint_as_float(f2tf32(acc[nt][3]));
            *(float2*)&sPh[rA*AST + nt*8 + 2*tg] = make_float2(h0, h1);
            *(float2*)&sPh[rB*AST + nt*8 + 2*tg] = make_float2(h2, h3);
            *(float2*)&sPl[rA*AST + nt*8 + 2*tg] = make_float2(
                __uint_as_float(f2tf32(acc[nt][0] - h0)),
                __uint_as_float(f2tf32(acc[nt][1] - h1)));
            *(float2*)&sPl[rB*AST + nt*8 + 2*tg] = make_float2(
                __uint_as_float(f2tf32(acc[nt][2] - h2)),
                __uint_as_float(f2tf32(acc[nt][3] - h3)));
        }
        __syncwarp();

        // ---- O += P V (pure LDS + mma) ----
        #pragma unroll
        for (int kk = 0; kk < 8; kk++) {
            const int k0 = kk*8;
            unsigned int ah0 = __float_as_uint(sPh[rA*AST + k0 + tg]);
            unsigned int ah1 = __float_as_uint(sPh[rB*AST + k0 + tg]);
            unsigned int ah2 = __float_as_uint(sPh[rA*AST + k0 + tg + 4]);
            unsigned int ah3 = __float_as_uint(sPh[rB*AST + k0 + tg + 4]);
            unsigned int al0 = __float_as_uint(sPl[rA*AST + k0 + tg]);
            unsigned int al1 = __float_as_uint(sPl[rB*AST + k0 + tg]);
            unsigned int al2 = __float_as_uint(sPl[rA*AST + k0 + tg + 4]);
            unsigned int al3 = __float_as_uint(sPl[rB*AST + k0 + tg + 4]);
            #pragma unroll
            for (int nt = 0; nt < 8; nt++) {
                const int n = nt*8 + g;
                unsigned int bh0 = __float_as_uint(sVh[(k0 + tg)*AST + n]);
                unsigned int bh1 = __float_as_uint(sVh[(k0 + tg + 4)*AST + n]);
                unsigned int bl0 = __float_as_uint(sVl[(k0 + tg)*AST + n]);
                unsigned int bl1 = __float_as_uint(sVl[(k0 + tg + 4)*AST + n]);
                mma_tf32(O[nt], ah0, ah1, ah2, ah3, bh0, bh1);
                mma_tf32(O[nt], ah0, ah1, ah2, ah3, bl0, bl1);
                mma_tf32(O[nt], al0, al1, al2, al3, bh0, bh1);
            }
        }
    }

    // ---- epilogue: scrambled layout R = h*256 + (i>>3), C = (i&7)*64 + d ----
    const int iA = i0 + rA, iB = i0 + rB;
    const unsigned int mkA = g_pmask[b*TLEN + iA];
    const unsigned int mkB = g_pmask[b*TLEN + iB];
    const float invA = 1.f / lA, invB = 1.f / lB;
    const size_t rowA = ((size_t)(b*TLEN) + h*256 + (iA >> 3))*EDIM + ((iA & 7) << 6);
    const size_t rowB = ((size_t)(b*TLEN) + h*256 + (iB >> 3))*EDIM + ((iB & 7) << 6);
    #pragma unroll
    for (int nt = 0; nt < 8; nt++) {
        const int d0 = nt*8 + 2*tg;
        float2 vm = *(const float2*)&g_vmean[(b*HEADS_N + h)*SDIM + d0];
        float2 oa = (mkA != 0u) ? make_float2(O[nt][0]*invA, O[nt][1]*invA) : vm;
        float2 ob = (mkB != 0u) ? make_float2(O[nt][2]*invB, O[nt][3]*invB) : vm;
        *(float2*)&g_attn[rowA + d0] = oa;
        *(float2*)&g_attn[rowB + d0] = ob;
    }
}

// ---------------- output projection: out = attnS @ Wo^T + bo -------------------
__global__ void outproj_kernel(const float* __restrict__ Wo,
                               const float* __restrict__ bo,
                               float* __restrict__ out) {
    __shared__ float sAt[64*64];
    __shared__ float sBt[64*64];
    const int m0 = blockIdx.x * 64;
    const int n0 = blockIdx.y * 64;
    const int tid = threadIdx.x;
    const int tx = tid & 15;
    const int ty = tid >> 4;

    float acc[4][4];
    #pragma unroll
    for (int r = 0; r < 4; r++)
        #pragma unroll
        for (int c = 0; c < 4; c++) acc[r][c] = 0.f;

    for (int kc = 0; kc < EDIM; kc += 64) {
        __syncthreads();
        for (int k = tid; k < 1024; k += 256) {
            int rr = k >> 4, c4 = k & 15;
            float4 a = *(const float4*)&g_attn[(size_t)(m0 + rr)*EDIM + kc + c4*4];
            int basea = c4*4*64 + (((rr >> 2) ^ c4) & 15)*4 + (rr & 3);
            sAt[basea]       = a.x;
            sAt[basea + 64]  = a.y;
            sAt[basea + 128] = a.z;
            sAt[basea + 192] = a.w;
            float4 bw = *(const float4*)&Wo[(size_t)(n0 + rr)*EDIM + kc + c4*4];
            sBt[basea]       = bw.x;
            sBt[basea + 64]  = bw.y;
            sBt[basea + 128] = bw.z;
            sBt[basea + 192] = bw.w;
        }
        __syncthreads();
        #pragma unroll 4
        for (int s4 = 0; s4 < 16; s4++) {
            const int ma = ((ty ^ s4) & 15)*4;
            const int mb = ((tx ^ s4) & 15)*4;
            #pragma unroll
            for (int j = 0; j < 4; j++) {
                const int s = s4*4 + j;
                float4 a4 = *(const float4*)&sAt[s*64 + ma];
                float4 b4 = *(const float4*)&sBt[s*64 + mb];
                float ra[4] = {a4.x, a4.y, a4.z, a4.w};
                float rb[4] = {b4.x, b4.y, b4.z, b4.w};
                #pragma unroll
                for (int r = 0; r < 4; r++)
                    #pragma unroll
                    for (int c = 0; c < 4; c++)
                        acc[r][c] = fmaf(ra[r], rb[c], acc[r][c]);
            }
        }
    }

    #pragma unroll
    for (int r = 0; r < 4; r++)
        #pragma unroll
        for (int c = 0; c < 4; c++)
            out[(size_t)(m0 + ty*4 + r)*EDIM + n0 + tx*4 + c] =
                acc[r][c] + bo[n0 + tx*4 + c];
}

// ---------------- launch ----------------
extern "C" void kernel_launch(void* const* d_in, const int* in_sizes, int n_in,
                              void* d_out, int out_size) {
    int idx_x = -1, idx_Er = -1, idx_Wo = -1, idx_bo = -1;
    int cand[8]; int ncand = 0;
    for (int scale = 1; scale <= 4; scale *= 4) {
        idx_x = idx_Er = idx_Wo = idx_bo = -1; ncand = 0;
        for (int i = 0; i < n_in; i++) {
            long long s = in_sizes[i];
            if      (s == (long long)BATCH*TLEN*EDIM*scale)   idx_x  = i;
            else if (s == (long long)HEADS_N*TLEN*SDIM*scale) idx_Er = i;
            else if (s == (long long)EDIM*EDIM*scale)         idx_Wo = i;
            else if (s == (long long)EDIM*scale)              idx_bo = i;
            else if (s == (long long)SDIM*SDIM*scale && ncand < 8) cand[ncand++] = i;
        }
        if (idx_x >= 0 && idx_Er >= 0 && idx_Wo >= 0 && idx_bo >= 0 && ncand == 4)
            break;
    }
    if (!(idx_x >= 0 && idx_Er >= 0 && idx_Wo >= 0 && idx_bo >= 0 && ncand == 4)) {
        int wi = (n_in >= 9) ? 3 : 2;
        idx_x = 0; cand[0] = 1; cand[1] = wi; cand[2] = wi + 1; cand[3] = wi + 2;
        idx_Er = wi + 3; idx_Wo = wi + 4; idx_bo = wi + 5; ncand = 4;
    }

    const float* x  = (const float*)d_in[idx_x];
    const float* Er = (const float*)d_in[idx_Er];
    const float* Wo = (const float*)d_in[idx_Wo];
    const float* bo = (const float*)d_in[idx_bo];
    float* out = (float*)d_out;

    const int PROJ_SMEM = (192*64 + 128*64) * (int)sizeof(float);   // 81920 B
    const int ATTN_SMEM = (6*64*AST) * (int)sizeof(float);          // 104448 B
    const int RG_SMEM   = (4*64*68) * (int)sizeof(float);           // 69632 B
    cudaFuncSetAttribute(proj_kernel, cudaFuncAttributeMaxDynamicSharedMemorySize, PROJ_SMEM);
    cudaFuncSetAttribute(attn_kernel, cudaFuncAttributeMaxDynamicSharedMemorySize, ATTN_SMEM);
    cudaFuncSetAttribute(relgemm_kernel, cudaFuncAttributeMaxDynamicSharedMemorySize, RG_SMEM);

    select_inputs<<<1, 256>>>((const float*)d_in[cand[0]], (const float*)d_in[cand[1]],
                              (const float*)d_in[cand[2]], (const float*)d_in[cand[3]],
                              (idx_x == 0) ? 1 : 0);
    proj_kernel<<<dim3(TLEN/128, HEADS_N, BATCH), 256, PROJ_SMEM>>>(x);
    relgemm_kernel<<<dim3(528, HEADS_N, BATCH), 256, RG_SMEM>>>(Er);
    vmean1_kernel<<<dim3(BATCH*HEADS_N, 8), 256>>>();
    vmean2_kernel<<<BATCH*HEADS_N, SDIM>>>();
    attn_kernel<<<dim3(TLEN/64, HEADS_N, BATCH), 128, ATTN_SMEM>>>();
    outproj_kernel<<<dim3((BATCH*TLEN)/64, EDIM/64), 256>>>(Wo, bo, out);
}

// round 11
// speedup vs baseline: 1.1186x; 1.1186x over previous
#include <cuda_runtime.h>
#include <math.h>

#define TLEN    2048
#define HEADS_N 8
#define BATCH   2
#define SDIM    64
#define EDIM    512
#define QE_BH   2162688   // 4096 * 528 floats per (b,h)
#define NCHUNK  144       // sum over it of ceil((it+1)/4)

// ---------------- scratch + resolved input pointers (device-resident) ----------
__device__ float g_q[BATCH*HEADS_N*TLEN*SDIM];
__device__ float g_k[BATCH*HEADS_N*TLEN*SDIM];
__device__ float g_v[BATCH*HEADS_N*TLEN*SDIM];
__device__ float g_vmean[BATCH*HEADS_N*SDIM];
__device__ float g_attn[BATCH*TLEN*EDIM];
__device__ float g_qe[BATCH*HEADS_N*QE_BH];   // triangular-packed QE bands
__device__ float g_pO[(size_t)BATCH*HEADS_N*NCHUNK*64*64];   // split-KV partials
__device__ float g_pm[BATCH*HEADS_N*NCHUNK*64];
__device__ float g_pl[BATCH*HEADS_N*NCHUNK*64];

__device__ const float*        g_pWq;
__device__ const float*        g_pWk;
__device__ const float*        g_pWv;
__device__ const unsigned int* g_pmask;

// ---------------- tf32 helpers ----------------
__device__ __forceinline__ unsigned int f2tf32(float x) {
    unsigned int r;
    asm("cvt.rna.tf32.f32 %0, %1;" : "=r"(r) : "f"(x));
    return r;
}
__device__ __forceinline__ void mma_tf32(float d[4],
        unsigned int a0, unsigned int a1, unsigned int a2, unsigned int a3,
        unsigned int b0, unsigned int b1) {
    asm("mma.sync.aligned.m16n8k8.row.col.f32.tf32.tf32.f32 "
        "{%0,%1,%2,%3}, {%4,%5,%6,%7}, {%8,%9}, {%0,%1,%2,%3};"
        : "+f"(d[0]), "+f"(d[1]), "+f"(d[2]), "+f"(d[3])
        : "r"(a0), "r"(a1), "r"(a2), "r"(a3), "r"(b0), "r"(b1));
}

// ---------------- prologue: content-based identification of mask ---------------
__global__ void select_inputs(const float* c0, const float* c1,
                              const float* c2, const float* c3, int x_first) {
    __shared__ int bad[4];
    const float* cand[4] = {c0, c1, c2, c3};
    if (threadIdx.x < 4) bad[threadIdx.x] = 0;
    __syncthreads();
    for (int j = 0; j < 4; j++) {
        const unsigned int* p = (const unsigned int*)cand[j];
        int b = 0;
        for (int i = threadIdx.x; i < SDIM*SDIM; i += blockDim.x) {
            unsigned int v = p[i];
            if (v != 0u && v != 1u && v != 0x3F800000u) { b = 1; break; }
        }
        if (b) atomicOr(&bad[j], 1);
    }
    __syncthreads();
    if (threadIdx.x == 0) {
        int mi = -1;
        for (int j = 0; j < 4; j++) if (!bad[j]) { mi = j; break; }
        if (mi < 0) mi = x_first ? 0 : 3;
        const float* rest[3]; int n = 0;
        for (int j = 0; j < 4; j++) if (j != mi) rest[n++] = cand[j];
        g_pmask = (const unsigned int*)cand[mi];
        if (x_first) { g_pWq = rest[0]; g_pWk = rest[1]; g_pWv = rest[2]; }
        else         { g_pWk = rest[0]; g_pWq = rest[1]; g_pWv = rest[2]; }
    }
}

// ---------------- QKV projection (swizzled float4 smem) ----------------
__global__ void proj_kernel(const float* __restrict__ x) {
    extern __shared__ float sm[];
    float* sW = sm;              // 192 rows x 64, swizzled
    float* sX = sm + 192*64;     // 128 rows x 64, swizzled
    const int t0 = blockIdx.x * 128;
    const int h  = blockIdx.y;
    const int b  = blockIdx.z;
    const int tid = threadIdx.x;
    const float* W[3] = {g_pWq, g_pWk, g_pWv};

    for (int k = tid; k < 3*64*16; k += 256) {
        int row = k >> 4, i4 = k & 15;
        int mm = row >> 6, o = row & 63;
        float4 f = *(const float4*)&W[mm][o*SDIM + i4*4];
        *(float4*)&sW[row*64 + ((i4 ^ o) & 15)*4] = f;
    }
    for (int k = tid; k < 128*16; k += 256) {
        int row = k >> 4, i4 = k & 15;
        float4 f = *(const float4*)&x[(size_t)(b*TLEN + t0 + row)*EDIM + h*SDIM + i4*4];
        *(float4*)&sX[row*64 + ((i4 ^ (row & 15)) & 15)*4] = f;
    }
    __syncthreads();

    for (int idx = tid; idx < 128*192; idx += 256) {
        int row = idx / 192;
        int rem = idx - row*192;
        float a = 0.f;
        const int mw = rem & 15;
        const int mx = row & 15;
        #pragma unroll
        for (int i4 = 0; i4 < 16; i4++) {
            float4 w4 = *(const float4*)&sW[rem*64 + ((i4 ^ mw) & 15)*4];
            float4 x4 = *(const float4*)&sX[row*64 + ((i4 ^ mx) & 15)*4];
            a = fmaf(w4.x, x4.x, a); a = fmaf(w4.y, x4.y, a);
            a = fmaf(w4.z, x4.z, a); a = fmaf(w4.w, x4.w, a);
        }
        int mm = rem >> 6, o = rem & 63;
        float* dst = (mm == 0) ? g_q : (mm == 1) ? g_k : g_v;
        dst[((size_t)(b*HEADS_N + h)*TLEN + t0 + row)*SDIM + o] = a;
    }
}

// ---------------- rel-pos GEMM (+ fused V-mean blocks at x==528) ----------------
__global__ void __launch_bounds__(256) relgemm_kernel(const float* __restrict__ Er) {
    extern __shared__ float sm[];
    const int tid = threadIdx.x;
    const int h = blockIdx.y, b = blockIdx.z;

    if (blockIdx.x == 528) {   // fused V-mean for (b,h)
        const int bh = b*HEADS_N + h;
        const int d = tid & 63, sub = tid >> 6;
        float a = 0.f;
        for (int l = sub; l < TLEN; l += 4)
            a += g_v[((size_t)bh*TLEN + l)*SDIM + d];
        sm[sub*64 + d] = a;
        __syncthreads();
        if (sub == 0)
            g_vmean[bh*SDIM + d] =
                (sm[d] + sm[64 + d] + sm[128 + d] + sm[192 + d]) * (1.f/(float)TLEN);
        return;
    }

    float* Qh = sm;              // [m=64][k] stride 68
    float* Ql = Qh + 64*68;
    float* Eh = Ql + 64*68;      // [k=64][n=o] stride 68
    float* El = Eh + 64*68;

    const int x = blockIdx.x;
    int it = (int)((sqrtf(8.f*(float)x + 1.f) - 1.f) * 0.5f);
    while ((it + 1)*(it + 2)/2 <= x) it++;
    while (it*(it + 1)/2 > x) it--;
    const int oc = x - it*(it + 1)/2;          // 0..it
    const int i0 = it * 64;
    const int j0 = TLEN - 64 - i0 + oc*64;     // Er row base (>= 0)

    const float* gq = g_q + (size_t)(b*HEADS_N + h)*TLEN*SDIM + (size_t)i0*SDIM;
    const float* ge = Er + (size_t)h*TLEN*SDIM;

    #pragma unroll
    for (int kk = 0; kk < 4; kk++) {
        int k = kk*256 + tid;
        int m = k >> 4, s4 = (k & 15)*4;
        float4 f = *(const float4*)&gq[m*SDIM + s4];
        float hx = __uint_as_float(f2tf32(f.x));
        float hy = __uint_as_float(f2tf32(f.y));
        float hz = __uint_as_float(f2tf32(f.z));
        float hw = __uint_as_float(f2tf32(f.w));
        *(float4*)&Qh[m*68 + s4] = make_float4(hx, hy, hz, hw);
        *(float4*)&Ql[m*68 + s4] = make_float4(
            __uint_as_float(f2tf32(f.x - hx)), __uint_as_float(f2tf32(f.y - hy)),
            __uint_as_float(f2tf32(f.z - hz)), __uint_as_float(f2tf32(f.w - hw)));
    }
    #pragma unroll
    for (int kk = 0; kk < 4; kk++) {
        int k = kk*256 + tid;
        int s4 = (k >> 6)*4, o = k & 63;
        float4 f = *(const float4*)&ge[(size_t)(j0 + o)*SDIM + s4];
        float hv[4], lv[4];
        float fv[4] = {f.x, f.y, f.z, f.w};
        #pragma unroll
        for (int i = 0; i < 4; i++) {
            hv[i] = __uint_as_float(f2tf32(fv[i]));
            lv[i] = __uint_as_float(f2tf32(fv[i] - hv[i]));
        }
        #pragma unroll
        for (int i = 0; i < 4; i++) {
            Eh[(s4 + i)*68 + o] = hv[i];
            El[(s4 + i)*68 + o] = lv[i];
        }
    }
    __syncthreads();

    const int w = tid >> 5, lane = tid & 31;
    const int g = lane >> 2, tg = lane & 3;
    const int mr = (w & 3)*16 + g;
    const int nb = (w >> 2)*32;

    float d[4][4];
    #pragma unroll
    for (int nt = 0; nt < 4; nt++)
        #pragma unroll
        for (int i = 0; i < 4; i++) d[nt][i] = 0.f;

    #pragma unroll
    for (int kk = 0; kk < 8; kk++) {
        const int k0 = kk*8;
        unsigned int ah0 = __float_as_uint(Qh[mr*68 + k0 + tg]);
        unsigned int ah1 = __float_as_uint(Qh[(mr + 8)*68 + k0 + tg]);
        unsigned int ah2 = __float_as_uint(Qh[mr*68 + k0 + tg + 4]);
        unsigned int ah3 = __float_as_uint(Qh[(mr + 8)*68 + k0 + tg + 4]);
        unsigned int al0 = __float_as_uint(Ql[mr*68 + k0 + tg]);
        unsigned int al1 = __float_as_uint(Ql[(mr + 8)*68 + k0 + tg]);
        unsigned int al2 = __float_as_uint(Ql[mr*68 + k0 + tg + 4]);
        unsigned int al3 = __float_as_uint(Ql[(mr + 8)*68 + k0 + tg + 4]);
        #pragma unroll
        for (int nt = 0; nt < 4; nt++) {
            const int n = nb + nt*8 + g;
            unsigned int bh0 = __float_as_uint(Eh[(k0 + tg)*68 + n]);
            unsigned int bh1 = __float_as_uint(Eh[(k0 + tg + 4)*68 + n]);
            unsigned int bl0 = __float_as_uint(El[(k0 + tg)*68 + n]);
            unsigned int bl1 = __float_as_uint(El[(k0 + tg + 4)*68 + n]);
            mma_tf32(d[nt], ah0, ah1, ah2, ah3, bh0, bh1);
            mma_tf32(d[nt], ah0, ah1, ah2, ah3, bl0, bl1);
            mma_tf32(d[nt], al0, al1, al2, al3, bh0, bh1);
        }
    }

    const int W = 64*(it + 1);
    float* qb = g_qe + (size_t)(b*HEADS_N + h)*QE_BH + (size_t)4096*(it*(it + 1)/2);
    const int colb = oc*64 + nb;
    #pragma unroll
    for (int nt = 0; nt < 4; nt++) {
        const int col = colb + nt*8 + 2*tg;
        *(float2*)&qb[(size_t)mr*W + col]       = make_float2(d[nt][0], d[nt][1]);
        *(float2*)&qb[(size_t)(mr + 8)*W + col] = make_float2(d[nt][2], d[nt][3]);
    }
}

// ---------------- split-KV tensor-core flash attention (partials) ---------------
// grid: (NCHUNK, H, B), 128 threads = 4 warps. Block = (i-tile it, chunk of <=4
// KV tiles). Writes un-normalized partial (m, l, O) per chunk; reduce merges.
#define AST 68   // 68 mod 32 == 4 -> all fragment LDS conflict-free
__global__ void __launch_bounds__(128, 3) attn_part_kernel() {
    extern __shared__ float sm[];
    float* sQ = sm;              // [i][s]  64 x AST
    float* sK = sQ + 64*AST;     // [c][s]  (pre-scaled)
    float* sV = sK + 64*AST;     // [lc][d]
    float* sP = sV + 64*AST;     // [i][lc]

    // decode block -> (it, chunk); heavy i-tiles first
    const int x = NCHUNK - 1 - (int)blockIdx.x;
    int it = 31, cb = 0;
    {
        int base = 0;
        for (int k = 0; k < 32; k++) {
            int nch = (k + 4) >> 2;            // ceil((k+1)/4)
            if (x < base + nch) { it = k; cb = base; break; }
            base += nch;
        }
    }
    const int chunk = x - cb;
    const int csta = chunk*4;
    const int cend = min(csta + 4, it + 1);
    const int i0 = it * 64;

    const int h  = blockIdx.y;
    const int b  = blockIdx.z;
    const int tid = threadIdx.x;
    const int w = tid >> 5, lane = tid & 31;
    const int g = lane >> 2, tg = lane & 3;
    const int rA = w*16 + g, rB = rA + 8;
    const float scale2 = 0.04419417382415922f;   // 512^-0.5

    const size_t bh = (size_t)(b*HEADS_N + h);
    const float* gq = g_q + bh*TLEN*SDIM;
    const float* gk = g_k + bh*TLEN*SDIM;
    const float* gv = g_v + bh*TLEN*SDIM;

    const int Wqe = 64*(it + 1);
    const float* qeb = g_qe + bh*QE_BH + (size_t)4096*(it*(it + 1)/2);
    const int omax = i0 + 63;

    // stage Q once
    for (int k = tid; k < 1024; k += 128) {
        int li = k >> 4, s4 = (k & 15)*4;
        *(float4*)&sQ[li*AST + s4] =
            *(const float4*)&gq[(size_t)(i0 + li)*SDIM + s4];
    }

    float mA = -1e30f, mB = -1e30f, lA = 0.f, lB = 0.f;
    float O[8][4];
    #pragma unroll
    for (int nt = 0; nt < 8; nt++)
        #pragma unroll
        for (int i = 0; i < 4; i++) O[nt][i] = 0.f;

    for (int ct = csta; ct < cend; ct++) {
        const int c0 = ct * 64;
        __syncthreads();
        for (int k = tid; k < 1024; k += 128) {
            int li = k >> 4, s4 = (k & 15)*4;
            float4 f = *(const float4*)&gk[(size_t)(c0 + li)*SDIM + s4];
            f.x *= scale2; f.y *= scale2; f.z *= scale2; f.w *= scale2;
            *(float4*)&sK[li*AST + s4] = f;
            *(float4*)&sV[li*AST + s4] =
                *(const float4*)&gv[(size_t)(c0 + li)*SDIM + s4];
        }
        __syncthreads();

        // ---- S = Q K^T (3x tf32) ----
        float acc[8][4];
        #pragma unroll
        for (int nt = 0; nt < 8; nt++)
            #pragma unroll
            for (int i = 0; i < 4; i++) acc[nt][i] = 0.f;

        #pragma unroll
        for (int kk = 0; kk < 8; kk++) {
            const int k0 = kk*8;
            float q0 = sQ[rA*AST + k0 + tg];
            float q1 = sQ[rB*AST + k0 + tg];
            float q2 = sQ[rA*AST + k0 + tg + 4];
            float q3 = sQ[rB*AST + k0 + tg + 4];
            unsigned int ah0 = f2tf32(q0), ah1 = f2tf32(q1);
            unsigned int ah2 = f2tf32(q2), ah3 = f2tf32(q3);
            unsigned int al0 = f2tf32(q0 - __uint_as_float(ah0));
            unsigned int al1 = f2tf32(q1 - __uint_as_float(ah1));
            unsigned int al2 = f2tf32(q2 - __uint_as_float(ah2));
            unsigned int al3 = f2tf32(q3 - __uint_as_float(ah3));
            #pragma unroll
            for (int nt = 0; nt < 8; nt++) {
                const int n = nt*8 + g;
                float b0f = sK[n*AST + k0 + tg];
                float b1f = sK[n*AST + k0 + tg + 4];
                unsigned int bh0 = f2tf32(b0f), bh1 = f2tf32(b1f);
                unsigned int bl0 = f2tf32(b0f - __uint_as_float(bh0));
                unsigned int bl1 = f2tf32(b1f - __uint_as_float(bh1));
                mma_tf32(acc[nt], ah0, ah1, ah2, ah3, bh0, bh1);
                mma_tf32(acc[nt], ah0, ah1, ah2, ah3, bl0, bl1);
                mma_tf32(acc[nt], al0, al1, al2, al3, bh0, bh1);
            }
        }

        // ---- add precomputed rel-pos band + causal mask ----
        #pragma unroll
        for (int nt = 0; nt < 8; nt++) {
            const int cl = nt*8 + 2*tg;
            const int oA = 63 - rA + c0 + cl;
            const int oB = 63 - rB + c0 + cl;
            if (oA     <= omax) acc[nt][0] += __ldg(qeb + (size_t)rA*Wqe + oA);
            if (oA + 1 <= omax) acc[nt][1] += __ldg(qeb + (size_t)rA*Wqe + oA + 1);
            if (oB     <= omax) acc[nt][2] += __ldg(qeb + (size_t)rB*Wqe + oB);
            if (oB + 1 <= omax) acc[nt][3] += __ldg(qeb + (size_t)rB*Wqe + oB + 1);
            if (ct == it) {
                if (cl     > rA) acc[nt][0] = -1e30f;
                if (cl + 1 > rA) acc[nt][1] = -1e30f;
                if (cl     > rB) acc[nt][2] = -1e30f;
                if (cl + 1 > rB) acc[nt][3] = -1e30f;
            }
        }

        // ---- online softmax (rows rA, rB; quad = lanes sharing g) ----
        float mxA = -1e30f, mxB = -1e30f;
        #pragma unroll
        for (int nt = 0; nt < 8; nt++) {
            mxA = fmaxf(mxA, fmaxf(acc[nt][0], acc[nt][1]));
            mxB = fmaxf(mxB, fmaxf(acc[nt][2], acc[nt][3]));
        }
        mxA = fmaxf(mxA, __shfl_xor_sync(0xffffffffu, mxA, 1));
        mxA = fmaxf(mxA, __shfl_xor_sync(0xffffffffu, mxA, 2));
        mxB = fmaxf(mxB, __shfl_xor_sync(0xffffffffu, mxB, 1));
        mxB = fmaxf(mxB, __shfl_xor_sync(0xffffffffu, mxB, 2));
        const float mnA = fmaxf(mA, mxA), mnB = fmaxf(mB, mxB);
        const float cA = __expf(mA - mnA), cB = __expf(mB - mnB);
        float sA = 0.f, sB = 0.f;
        #pragma unroll
        for (int nt = 0; nt < 8; nt++) {
            acc[nt][0] = __expf(acc[nt][0] - mnA);
            acc[nt][1] = __expf(acc[nt][1] - mnA);
            acc[nt][2] = __expf(acc[nt][2] - mnB);
            acc[nt][3] = __expf(acc[nt][3] - mnB);
            sA += acc[nt][0] + acc[nt][1];
            sB += acc[nt][2] + acc[nt][3];
        }
        sA += __shfl_xor_sync(0xffffffffu, sA, 1);
        sA += __shfl_xor_sync(0xffffffffu, sA, 2);
        sB += __shfl_xor_sync(0xffffffffu, sB, 1);
        sB += __shfl_xor_sync(0xffffffffu, sB, 2);
        lA = lA*cA + sA;  mA = mnA;
        lB = lB*cB + sB;  mB = mnB;
        #pragma unroll
        for (int nt = 0; nt < 8; nt++) {
            O[nt][0] *= cA; O[nt][1] *= cA;
            O[nt][2] *= cB; O[nt][3] *= cB;
        }

        // ---- re-layout P via warp-private smem rows ----
        #pragma unroll
        for (int nt = 0; nt < 8; nt++) {
            *(float2*)&sP[rA*AST + nt*8 + 2*tg] = make_float2(acc[nt][0], acc[nt][1]);
            *(float2*)&sP[rB*AST + nt*8 + 2*tg] = make_float2(acc[nt][2], acc[nt][3]);
        }
        __syncwarp();

        // ---- O += P V (3x tf32) ----
        #pragma unroll
        for (int kk = 0; kk < 8; kk++) {
            const int k0 = kk*8;
            float p0 = sP[rA*AST + k0 + tg];
            float p1 = sP[rB*AST + k0 + tg];
            float p2 = sP[rA*AST + k0 + tg + 4];
            float p3 = sP[rB*AST + k0 + tg + 4];
            unsigned int ah0 = f2tf32(p0), ah1 = f2tf32(p1);
            unsigned int ah2 = f2tf32(p2), ah3 = f2tf32(p3);
            unsigned int al0 = f2tf32(p0 - __uint_as_float(ah0));
            unsigned int al1 = f2tf32(p1 - __uint_as_float(ah1));
            unsigned int al2 = f2tf32(p2 - __uint_as_float(ah2));
            unsigned int al3 = f2tf32(p3 - __uint_as_float(ah3));
            #pragma unroll
            for (int nt = 0; nt < 8; nt++) {
                const int n = nt*8 + g;
                float b0f = sV[(k0 + tg)*AST + n];
                float b1f = sV[(k0 + tg + 4)*AST + n];
                unsigned int bh0 = f2tf32(b0f), bh1 = f2tf32(b1f);
                unsigned int bl0 = f2tf32(b0f - __uint_as_float(bh0));
                unsigned int bl1 = f2tf32(b1f - __uint_as_float(bh1));
                mma_tf32(O[nt], ah0, ah1, ah2, ah3, bh0, bh1);
                mma_tf32(O[nt], ah0, ah1, ah2, ah3, bl0, bl1);
                mma_tf32(O[nt], al0, al1, al2, al3, bh0, bh1);
            }
        }
    }

    // ---- write partials ----
    const int slot = (int)(bh*NCHUNK) + cb + chunk;
    float* pO = g_pO + (size_t)slot*64*64;
    #pragma unroll
    for (int nt = 0; nt < 8; nt++) {
        *(float2*)&pO[rA*64 + nt*8 + 2*tg] = make_float2(O[nt][0], O[nt][1]);
        *(float2*)&pO[rB*64 + nt*8 + 2*tg] = make_float2(O[nt][2], O[nt][3]);
    }
    if (tg == 0) {
        g_pm[slot*64 + rA] = mA;  g_pl[slot*64 + rA] = lA;
        g_pm[slot*64 + rB] = mB;  g_pl[slot*64 + rB] = lB;
    }
}

// ---------------- split-KV reduce: merge partials, mask, scramble --------------
__global__ void __launch_bounds__(128) reduce_kernel() {
    const int it = blockIdx.x, h = blockIdx.y, b = blockIdx.z;
    int base = 0;
    for (int k = 0; k < it; k++) base += (k + 4) >> 2;
    const int nc = (it + 4) >> 2;
    const int slot0 = (b*HEADS_N + h)*NCHUNK + base;
    const int tid = threadIdx.x;
    const int row = tid >> 1;
    const int half = (tid & 1)*32;

    float mstar = -1e30f;
    for (int p = 0; p < nc; p++)
        mstar = fmaxf(mstar, g_pm[(slot0 + p)*64 + row]);

    float lstar = 0.f;
    float Oa[32];
    #pragma unroll
    for (int d = 0; d < 32; d++) Oa[d] = 0.f;

    for (int p = 0; p < nc; p++) {
        const float f = __expf(g_pm[(slot0 + p)*64 + row] - mstar);
        lstar += g_pl[(slot0 + p)*64 + row] * f;
        const float* po = g_pO + ((size_t)(slot0 + p)*64 + row)*64 + half;
        #pragma unroll
        for (int d4 = 0; d4 < 8; d4++) {
            float4 v = *(const float4*)&po[d4*4];
            Oa[d4*4 + 0] += f*v.x;
            Oa[d4*4 + 1] += f*v.y;
            Oa[d4*4 + 2] += f*v.z;
            Oa[d4*4 + 3] += f*v.w;
        }
    }

    const int i = it*64 + row;
    const unsigned int mk = g_pmask[b*TLEN + i];
    const float inv = 1.f / lstar;
    float* dst = &g_attn[((size_t)(b*TLEN) + h*256 + (i >> 3))*EDIM
                         + ((i & 7) << 6) + half];
    if (mk != 0u) {
        #pragma unroll
        for (int d = 0; d < 32; d++) dst[d] = Oa[d]*inv;
    } else {
        const float* vm = &g_vmean[(b*HEADS_N + h)*SDIM + half];
        #pragma unroll
        for (int d = 0; d < 32; d++) dst[d] = vm[d];
    }
}

// ---------------- output projection: out = attnS @ Wo^T + bo -------------------
__global__ void outproj_kernel(const float* __restrict__ Wo,
                               const float* __restrict__ bo,
                               float* __restrict__ out) {
    __shared__ float sAt[64*64];
    __shared__ float sBt[64*64];
    const int m0 = blockIdx.x * 64;
    const int n0 = blockIdx.y * 64;
    const int tid = threadIdx.x;
    const int tx = tid & 15;
    const int ty = tid >> 4;

    float acc[4][4];
    #pragma unroll
    for (int r = 0; r < 4; r++)
        #pragma unroll
        for (int c = 0; c < 4; c++) acc[r][c] = 0.f;

    for (int kc = 0; kc < EDIM; kc += 64) {
        __syncthreads();
        for (int k = tid; k < 1024; k += 256) {
            int rr = k >> 4, c4 = k & 15;
            float4 a = *(const float4*)&g_attn[(size_t)(m0 + rr)*EDIM + kc + c4*4];
            int basea = c4*4*64 + (((rr >> 2) ^ c4) & 15)*4 + (rr & 3);
            sAt[basea]       = a.x;
            sAt[basea + 64]  = a.y;
            sAt[basea + 128] = a.z;
            sAt[basea + 192] = a.w;
            float4 bw = *(const float4*)&Wo[(size_t)(n0 + rr)*EDIM + kc + c4*4];
            sBt[basea]       = bw.x;
            sBt[basea + 64]  = bw.y;
            sBt[basea + 128] = bw.z;
            sBt[basea + 192] = bw.w;
        }
        __syncthreads();
        #pragma unroll 4
        for (int s4 = 0; s4 < 16; s4++) {
            const int ma = ((ty ^ s4) & 15)*4;
            const int mb = ((tx ^ s4) & 15)*4;
            #pragma unroll
            for (int j = 0; j < 4; j++) {
                const int s = s4*4 + j;
                float4 a4 = *(const float4*)&sAt[s*64 + ma];
                float4 b4 = *(const float4*)&sBt[s*64 + mb];
                float ra[4] = {a4.x, a4.y, a4.z, a4.w};
                float rb[4] = {b4.x, b4.y, b4.z, b4.w};
                #pragma unroll
                for (int r = 0; r < 4; r++)
                    #pragma unroll
                    for (int c = 0; c < 4; c++)
                        acc[r][c] = fmaf(ra[r], rb[c], acc[r][c]);
            }
        }
    }

    #pragma unroll
    for (int r = 0; r < 4; r++)
        #pragma unroll
        for (int c = 0; c < 4; c++)
            out[(size_t)(m0 + ty*4 + r)*EDIM + n0 + tx*4 + c] =
                acc[r][c] + bo[n0 + tx*4 + c];
}

// ---------------- launch ----------------
extern "C" void kernel_launch(void* const* d_in, const int* in_sizes, int n_in,
                              void* d_out, int out_size) {
    int idx_x = -1, idx_Er = -1, idx_Wo = -1, idx_bo = -1;
    int cand[8]; int ncand = 0;
    for (int scale = 1; scale <= 4; scale *= 4) {
        idx_x = idx_Er = idx_Wo = idx_bo = -1; ncand = 0;
        for (int i = 0; i < n_in; i++) {
            long long s = in_sizes[i];
            if      (s == (long long)BATCH*TLEN*EDIM*scale)   idx_x  = i;
            else if (s == (long long)HEADS_N*TLEN*SDIM*scale) idx_Er = i;
            else if (s == (long long)EDIM*EDIM*scale)         idx_Wo = i;
            else if (s == (long long)EDIM*scale)              idx_bo = i;
            else if (s == (long long)SDIM*SDIM*scale && ncand < 8) cand[ncand++] = i;
        }
        if (idx_x >= 0 && idx_Er >= 0 && idx_Wo >= 0 && idx_bo >= 0 && ncand == 4)
            break;
    }
    if (!(idx_x >= 0 && idx_Er >= 0 && idx_Wo >= 0 && idx_bo >= 0 && ncand == 4)) {
        int wi = (n_in >= 9) ? 3 : 2;
        idx_x = 0; cand[0] = 1; cand[1] = wi; cand[2] = wi + 1; cand[3] = wi + 2;
        idx_Er = wi + 3; idx_Wo = wi + 4; idx_bo = wi + 5; ncand = 4;
    }

    const float* x  = (const float*)d_in[idx_x];
    const float* Er = (const float*)d_in[idx_Er];
    const float* Wo = (const float*)d_in[idx_Wo];
    const float* bo = (const float*)d_in[idx_bo];
    float* out = (float*)d_out;

    const int PROJ_SMEM = (192*64 + 128*64) * (int)sizeof(float);   // 81920 B
    const int ATTN_SMEM = (4*64*AST) * (int)sizeof(float);          // 69632 B
    const int RG_SMEM   = (4*64*68) * (int)sizeof(float);           // 69632 B
    cudaFuncSetAttribute(proj_kernel, cudaFuncAttributeMaxDynamicSharedMemorySize, PROJ_SMEM);
    cudaFuncSetAttribute(attn_part_kernel, cudaFuncAttributeMaxDynamicSharedMemorySize, ATTN_SMEM);
    cudaFuncSetAttribute(relgemm_kernel, cudaFuncAttributeMaxDynamicSharedMemorySize, RG_SMEM);

    select_inputs<<<1, 256>>>((const float*)d_in[cand[0]], (const float*)d_in[cand[1]],
                              (const float*)d_in[cand[2]], (const float*)d_in[cand[3]],
                              (idx_x == 0) ? 1 : 0);
    proj_kernel<<<dim3(TLEN/128, HEADS_N, BATCH), 256, PROJ_SMEM>>>(x);
    relgemm_kernel<<<dim3(529, HEADS_N, BATCH), 256, RG_SMEM>>>(Er);
    attn_part_kernel<<<dim3(NCHUNK, HEADS_N, BATCH), 128, ATTN_SMEM>>>();
    reduce_kernel<<<dim3(TLEN/64, HEADS_N, BATCH), 128>>>();
    outproj_kernel<<<dim3((BATCH*TLEN)/64, EDIM/64), 256>>>(Wo, bo, out);
}

// round 12
// speedup vs baseline: 1.2590x; 1.1255x over previous
#include <cuda_runtime.h>
#include <math.h>

#define TLEN    2048
#define HEADS_N 8
#define BATCH   2
#define SDIM    64
#define EDIM    512
#define QE_BH   2162688   // 4096 * 528 floats per (b,h)
#define NCHUNK  144       // sum over it of ceil((it+1)/4)

// ---------------- scratch + resolved input pointers (device-resident) ----------
__device__ float g_q[BATCH*HEADS_N*TLEN*SDIM];
__device__ float g_k[BATCH*HEADS_N*TLEN*SDIM];
__device__ float g_v[BATCH*HEADS_N*TLEN*SDIM];
__device__ float g_vmean[BATCH*HEADS_N*SDIM];
__device__ float g_attn[BATCH*TLEN*EDIM];
__device__ float g_qe[BATCH*HEADS_N*QE_BH];   // triangular-packed QE bands
__device__ float g_pO[(size_t)BATCH*HEADS_N*NCHUNK*64*64];   // split-KV partials
__device__ float g_pm[BATCH*HEADS_N*NCHUNK*64];
__device__ float g_pl[BATCH*HEADS_N*NCHUNK*64];

__device__ const float*        g_pWq;
__device__ const float*        g_pWk;
__device__ const float*        g_pWv;
__device__ const unsigned int* g_pmask;

// ---------------- tf32 helpers ----------------
__device__ __forceinline__ unsigned int f2tf32(float x) {
    unsigned int r;
    asm("cvt.rna.tf32.f32 %0, %1;" : "=r"(r) : "f"(x));
    return r;
}
__device__ __forceinline__ void mma_tf32(float d[4],
        unsigned int a0, unsigned int a1, unsigned int a2, unsigned int a3,
        unsigned int b0, unsigned int b1) {
    asm("mma.sync.aligned.m16n8k8.row.col.f32.tf32.tf32.f32 "
        "{%0,%1,%2,%3}, {%4,%5,%6,%7}, {%8,%9}, {%0,%1,%2,%3};"
        : "+f"(d[0]), "+f"(d[1]), "+f"(d[2]), "+f"(d[3])
        : "r"(a0), "r"(a1), "r"(a2), "r"(a3), "r"(b0), "r"(b1));
}

// ---------------- prologue: content-based identification of mask ---------------
__global__ void select_inputs(const float* c0, const float* c1,
                              const float* c2, const float* c3, int x_first) {
    __shared__ int bad[4];
    const float* cand[4] = {c0, c1, c2, c3};
    if (threadIdx.x < 4) bad[threadIdx.x] = 0;
    __syncthreads();
    for (int j = 0; j < 4; j++) {
        const unsigned int* p = (const unsigned int*)cand[j];
        int b = 0;
        for (int i = threadIdx.x; i < SDIM*SDIM; i += blockDim.x) {
            unsigned int v = p[i];
            if (v != 0u && v != 1u && v != 0x3F800000u) { b = 1; break; }
        }
        if (b) atomicOr(&bad[j], 1);
    }
    __syncthreads();
    if (threadIdx.x == 0) {
        int mi = -1;
        for (int j = 0; j < 4; j++) if (!bad[j]) { mi = j; break; }
        if (mi < 0) mi = x_first ? 0 : 3;
        const float* rest[3]; int n = 0;
        for (int j = 0; j < 4; j++) if (j != mi) rest[n++] = cand[j];
        g_pmask = (const unsigned int*)cand[mi];
        if (x_first) { g_pWq = rest[0]; g_pWk = rest[1]; g_pWv = rest[2]; }
        else         { g_pWk = rest[0]; g_pWq = rest[1]; g_pWv = rest[2]; }
    }
}

// ---------------- QKV projection (swizzled float4 smem) ----------------
__global__ void proj_kernel(const float* __restrict__ x) {
    extern __shared__ float sm[];
    float* sW = sm;              // 192 rows x 64, swizzled
    float* sX = sm + 192*64;     // 128 rows x 64, swizzled
    const int t0 = blockIdx.x * 128;
    const int h  = blockIdx.y;
    const int b  = blockIdx.z;
    const int tid = threadIdx.x;
    const float* W[3] = {g_pWq, g_pWk, g_pWv};

    for (int k = tid; k < 3*64*16; k += 256) {
        int row = k >> 4, i4 = k & 15;
        int mm = row >> 6, o = row & 63;
        float4 f = *(const float4*)&W[mm][o*SDIM + i4*4];
        *(float4*)&sW[row*64 + ((i4 ^ o) & 15)*4] = f;
    }
    for (int k = tid; k < 128*16; k += 256) {
        int row = k >> 4, i4 = k & 15;
        float4 f = *(const float4*)&x[(size_t)(b*TLEN + t0 + row)*EDIM + h*SDIM + i4*4];
        *(float4*)&sX[row*64 + ((i4 ^ (row & 15)) & 15)*4] = f;
    }
    __syncthreads();

    for (int idx = tid; idx < 128*192; idx += 256) {
        int row = idx / 192;
        int rem = idx - row*192;
        float a = 0.f;
        const int mw = rem & 15;
        const int mx = row & 15;
        #pragma unroll
        for (int i4 = 0; i4 < 16; i4++) {
            float4 w4 = *(const float4*)&sW[rem*64 + ((i4 ^ mw) & 15)*4];
            float4 x4 = *(const float4*)&sX[row*64 + ((i4 ^ mx) & 15)*4];
            a = fmaf(w4.x, x4.x, a); a = fmaf(w4.y, x4.y, a);
            a = fmaf(w4.z, x4.z, a); a = fmaf(w4.w, x4.w, a);
        }
        int mm = rem >> 6, o = rem & 63;
        float* dst = (mm == 0) ? g_q : (mm == 1) ? g_k : g_v;
        dst[((size_t)(b*HEADS_N + h)*TLEN + t0 + row)*SDIM + o] = a;
    }
}

// ---------------- rel-pos GEMM v2: chunked, natural-layout B ----------------
// Block = (i-tile it, chunk of <=4 oc tiles). QE[m][o] = Q[m][:] . Er[j0+o][:]
// = A(row) x B(col) with B = Er rows taken natively ([n][k]). Q hi/lo staged
// ONCE per block; each oc stages one Er tile hi/lo (no transpose).
// grid: (NCHUNK+1, H, B); x==NCHUNK does the fused V-mean for (b,h).
__global__ void __launch_bounds__(256) relgemm_kernel(const float* __restrict__ Er) {
    extern __shared__ float sm[];
    const int tid = threadIdx.x;
    const int h = blockIdx.y, b = blockIdx.z;

    if (blockIdx.x == NCHUNK) {   // fused V-mean for (b,h)
        const int bh = b*HEADS_N + h;
        const int d = tid & 63, sub = tid >> 6;
        float a = 0.f;
        for (int l = sub; l < TLEN; l += 4)
            a += g_v[((size_t)bh*TLEN + l)*SDIM + d];
        sm[sub*64 + d] = a;
        __syncthreads();
        if (sub == 0)
            g_vmean[bh*SDIM + d] =
                (sm[d] + sm[64 + d] + sm[128 + d] + sm[192 + d]) * (1.f/(float)TLEN);
        return;
    }

    float* Qh = sm;              // [m=64][k] stride 68
    float* Ql = Qh + 64*68;
    float* Eh = Ql + 64*68;      // [n=o][k=s] natural rows, stride 68
    float* El = Eh + 64*68;

    // decode x -> (it, chunk)
    const int x = (int)blockIdx.x;
    int it = 31, cb = 0;
    {
        int base = 0;
        for (int k = 0; k < 32; k++) {
            int nch = (k + 4) >> 2;
            if (x < base + nch) { it = k; cb = base; break; }
            base += nch;
        }
    }
    const int chunk = x - cb;
    const int osta = chunk*4;
    const int oend = min(osta + 4, it + 1);
    const int i0 = it * 64;

    const float* gq = g_q + (size_t)(b*HEADS_N + h)*TLEN*SDIM + (size_t)i0*SDIM;
    const float* ge = Er + (size_t)h*TLEN*SDIM;

    // stage Q hi/lo once
    #pragma unroll
    for (int kk = 0; kk < 4; kk++) {
        int k = kk*256 + tid;
        int m = k >> 4, s4 = (k & 15)*4;
        float4 f = *(const float4*)&gq[m*SDIM + s4];
        float hx = __uint_as_float(f2tf32(f.x));
        float hy = __uint_as_float(f2tf32(f.y));
        float hz = __uint_as_float(f2tf32(f.z));
        float hw = __uint_as_float(f2tf32(f.w));
        *(float4*)&Qh[m*68 + s4] = make_float4(hx, hy, hz, hw);
        *(float4*)&Ql[m*68 + s4] = make_float4(
            __uint_as_float(f2tf32(f.x - hx)), __uint_as_float(f2tf32(f.y - hy)),
            __uint_as_float(f2tf32(f.z - hz)), __uint_as_float(f2tf32(f.w - hw)));
    }

    const int w = tid >> 5, lane = tid & 31;
    const int g = lane >> 2, tg = lane & 3;
    const int mr = (w & 3)*16 + g;
    const int nb = (w >> 2)*32;

    const int W = 64*(it + 1);
    float* qb = g_qe + (size_t)(b*HEADS_N + h)*QE_BH + (size_t)4096*(it*(it + 1)/2);

    for (int oc = osta; oc < oend; oc++) {
        const int j0 = TLEN - 64 - i0 + oc*64;     // Er row base; j0+63 <= TLEN-1
        __syncthreads();   // previous E tile fully consumed (covers Q staging too)
        #pragma unroll
        for (int kk = 0; kk < 4; kk++) {
            int k = kk*256 + tid;
            int o = k >> 4, s4 = (k & 15)*4;
            float4 f = *(const float4*)&ge[(size_t)(j0 + o)*SDIM + s4];
            float hx = __uint_as_float(f2tf32(f.x));
            float hy = __uint_as_float(f2tf32(f.y));
            float hz = __uint_as_float(f2tf32(f.z));
            float hw = __uint_as_float(f2tf32(f.w));
            *(float4*)&Eh[o*68 + s4] = make_float4(hx, hy, hz, hw);
            *(float4*)&El[o*68 + s4] = make_float4(
                __uint_as_float(f2tf32(f.x - hx)), __uint_as_float(f2tf32(f.y - hy)),
                __uint_as_float(f2tf32(f.z - hz)), __uint_as_float(f2tf32(f.w - hw)));
        }
        __syncthreads();

        float d[4][4];
        #pragma unroll
        for (int nt = 0; nt < 4; nt++)
            #pragma unroll
            for (int i = 0; i < 4; i++) d[nt][i] = 0.f;

        #pragma unroll
        for (int kk = 0; kk < 8; kk++) {
            const int k0 = kk*8;
            unsigned int ah0 = __float_as_uint(Qh[mr*68 + k0 + tg]);
            unsigned int ah1 = __float_as_uint(Qh[(mr + 8)*68 + k0 + tg]);
            unsigned int ah2 = __float_as_uint(Qh[mr*68 + k0 + tg + 4]);
            unsigned int ah3 = __float_as_uint(Qh[(mr + 8)*68 + k0 + tg + 4]);
            unsigned int al0 = __float_as_uint(Ql[mr*68 + k0 + tg]);
            unsigned int al1 = __float_as_uint(Ql[(mr + 8)*68 + k0 + tg]);
            unsigned int al2 = __float_as_uint(Ql[mr*68 + k0 + tg + 4]);
            unsigned int al3 = __float_as_uint(Ql[(mr + 8)*68 + k0 + tg + 4]);
            #pragma unroll
            for (int nt = 0; nt < 4; nt++) {
                const int n = nb + nt*8 + g;
                unsigned int bh0 = __float_as_uint(Eh[n*68 + k0 + tg]);
                unsigned int bh1 = __float_as_uint(Eh[n*68 + k0 + tg + 4]);
                unsigned int bl0 = __float_as_uint(El[n*68 + k0 + tg]);
                unsigned int bl1 = __float_as_uint(El[n*68 + k0 + tg + 4]);
                mma_tf32(d[nt], ah0, ah1, ah2, ah3, bh0, bh1);
                mma_tf32(d[nt], ah0, ah1, ah2, ah3, bl0, bl1);
                mma_tf32(d[nt], al0, al1, al2, al3, bh0, bh1);
            }
        }

        const int colb = oc*64 + nb;
        #pragma unroll
        for (int nt = 0; nt < 4; nt++) {
            const int col = colb + nt*8 + 2*tg;
            *(float2*)&qb[(size_t)mr*W + col]       = make_float2(d[nt][0], d[nt][1]);
            *(float2*)&qb[(size_t)(mr + 8)*W + col] = make_float2(d[nt][2], d[nt][3]);
        }
    }
}

// ---------------- split-KV tensor-core flash attention (partials) ---------------
#define AST 68   // 68 mod 32 == 4 -> all fragment LDS conflict-free
__global__ void __launch_bounds__(128, 3) attn_part_kernel() {
    extern __shared__ float sm[];
    float* sQ = sm;              // [i][s]  64 x AST
    float* sK = sQ + 64*AST;     // [c][s]  (pre-scaled)
    float* sV = sK + 64*AST;     // [lc][d]
    float* sP = sV + 64*AST;     // [i][lc]

    const int x = NCHUNK - 1 - (int)blockIdx.x;   // heavy i-tiles first
    int it = 31, cb = 0;
    {
        int base = 0;
        for (int k = 0; k < 32; k++) {
            int nch = (k + 4) >> 2;
            if (x < base + nch) { it = k; cb = base; break; }
            base += nch;
        }
    }
    const int chunk = x - cb;
    const int csta = chunk*4;
    const int cend = min(csta + 4, it + 1);
    const int i0 = it * 64;

    const int h  = blockIdx.y;
    const int b  = blockIdx.z;
    const int tid = threadIdx.x;
    const int w = tid >> 5, lane = tid & 31;
    const int g = lane >> 2, tg = lane & 3;
    const int rA = w*16 + g, rB = rA + 8;
    const float scale2 = 0.04419417382415922f;   // 512^-0.5

    const size_t bh = (size_t)(b*HEADS_N + h);
    const float* gq = g_q + bh*TLEN*SDIM;
    const float* gk = g_k + bh*TLEN*SDIM;
    const float* gv = g_v + bh*TLEN*SDIM;

    const int Wqe = 64*(it + 1);
    const float* qeb = g_qe + bh*QE_BH + (size_t)4096*(it*(it + 1)/2);
    const int omax = i0 + 63;

    for (int k = tid; k < 1024; k += 128) {
        int li = k >> 4, s4 = (k & 15)*4;
        *(float4*)&sQ[li*AST + s4] =
            *(const float4*)&gq[(size_t)(i0 + li)*SDIM + s4];
    }

    float mA = -1e30f, mB = -1e30f, lA = 0.f, lB = 0.f;
    float O[8][4];
    #pragma unroll
    for (int nt = 0; nt < 8; nt++)
        #pragma unroll
        for (int i = 0; i < 4; i++) O[nt][i] = 0.f;

    for (int ct = csta; ct < cend; ct++) {
        const int c0 = ct * 64;
        __syncthreads();
        for (int k = tid; k < 1024; k += 128) {
            int li = k >> 4, s4 = (k & 15)*4;
            float4 f = *(const float4*)&gk[(size_t)(c0 + li)*SDIM + s4];
            f.x *= scale2; f.y *= scale2; f.z *= scale2; f.w *= scale2;
            *(float4*)&sK[li*AST + s4] = f;
            *(float4*)&sV[li*AST + s4] =
                *(const float4*)&gv[(size_t)(c0 + li)*SDIM + s4];
        }
        __syncthreads();

        float acc[8][4];
        #pragma unroll
        for (int nt = 0; nt < 8; nt++)
            #pragma unroll
            for (int i = 0; i < 4; i++) acc[nt][i] = 0.f;

        #pragma unroll
        for (int kk = 0; kk < 8; kk++) {
            const int k0 = kk*8;
            float q0 = sQ[rA*AST + k0 + tg];
            float q1 = sQ[rB*AST + k0 + tg];
            float q2 = sQ[rA*AST + k0 + tg + 4];
            float q3 = sQ[rB*AST + k0 + tg + 4];
            unsigned int ah0 = f2tf32(q0), ah1 = f2tf32(q1);
            unsigned int ah2 = f2tf32(q2), ah3 = f2tf32(q3);
            unsigned int al0 = f2tf32(q0 - __uint_as_float(ah0));
            unsigned int al1 = f2tf32(q1 - __uint_as_float(ah1));
            unsigned int al2 = f2tf32(q2 - __uint_as_float(ah2));
            unsigned int al3 = f2tf32(q3 - __uint_as_float(ah3));
            #pragma unroll
            for (int nt = 0; nt < 8; nt++) {
                const int n = nt*8 + g;
                float b0f = sK[n*AST + k0 + tg];
                float b1f = sK[n*AST + k0 + tg + 4];
                unsigned int bh0 = f2tf32(b0f), bh1 = f2tf32(b1f);
                unsigned int bl0 = f2tf32(b0f - __uint_as_float(bh0));
                unsigned int bl1 = f2tf32(b1f - __uint_as_float(bh1));
                mma_tf32(acc[nt], ah0, ah1, ah2, ah3, bh0, bh1);
                mma_tf32(acc[nt], ah0, ah1, ah2, ah3, bl0, bl1);
                mma_tf32(acc[nt], al0, al1, al2, al3, bh0, bh1);
            }
        }

        #pragma unroll
        for (int nt = 0; nt < 8; nt++) {
            const int cl = nt*8 + 2*tg;
            const int oA = 63 - rA + c0 + cl;
            const int oB = 63 - rB + c0 + cl;
            if (oA     <= omax) acc[nt][0] += __ldg(qeb + (size_t)rA*Wqe + oA);
            if (oA + 1 <= omax) acc[nt][1] += __ldg(qeb + (size_t)rA*Wqe + oA + 1);
            if (oB     <= omax) acc[nt][2] += __ldg(qeb + (size_t)rB*Wqe + oB);
            if (oB + 1 <= omax) acc[nt][3] += __ldg(qeb + (size_t)rB*Wqe + oB + 1);
            if (ct == it) {
                if (cl     > rA) acc[nt][0] = -1e30f;
                if (cl + 1 > rA) acc[nt][1] = -1e30f;
                if (cl     > rB) acc[nt][2] = -1e30f;
                if (cl + 1 > rB) acc[nt][3] = -1e30f;
            }
        }

        float mxA = -1e30f, mxB = -1e30f;
        #pragma unroll
        for (int nt = 0; nt < 8; nt++) {
            mxA = fmaxf(mxA, fmaxf(acc[nt][0], acc[nt][1]));
            mxB = fmaxf(mxB, fmaxf(acc[nt][2], acc[nt][3]));
        }
        mxA = fmaxf(mxA, __shfl_xor_sync(0xffffffffu, mxA, 1));
        mxA = fmaxf(mxA, __shfl_xor_sync(0xffffffffu, mxA, 2));
        mxB = fmaxf(mxB, __shfl_xor_sync(0xffffffffu, mxB, 1));
        mxB = fmaxf(mxB, __shfl_xor_sync(0xffffffffu, mxB, 2));
        const float mnA = fmaxf(mA, mxA), mnB = fmaxf(mB, mxB);
        const float cA = __expf(mA - mnA), cB = __expf(mB - mnB);
        float sA = 0.f, sB = 0.f;
        #pragma unroll
        for (int nt = 0; nt < 8; nt++) {
            acc[nt][0] = __expf(acc[nt][0] - mnA);
            acc[nt][1] = __expf(acc[nt][1] - mnA);
            acc[nt][2] = __expf(acc[nt][2] - mnB);
            acc[nt][3] = __expf(acc[nt][3] - mnB);
            sA += acc[nt][0] + acc[nt][1];
            sB += acc[nt][2] + acc[nt][3];
        }
        sA += __shfl_xor_sync(0xffffffffu, sA, 1);
        sA += __shfl_xor_sync(0xffffffffu, sA, 2);
        sB += __shfl_xor_sync(0xffffffffu, sB, 1);
        sB += __shfl_xor_sync(0xffffffffu, sB, 2);
        lA = lA*cA + sA;  mA = mnA;
        lB = lB*cB + sB;  mB = mnB;
        #pragma unroll
        for (int nt = 0; nt < 8; nt++) {
            O[nt][0] *= cA; O[nt][1] *= cA;
            O[nt][2] *= cB; O[nt][3] *= cB;
        }

        #pragma unroll
        for (int nt = 0; nt < 8; nt++) {
            *(float2*)&sP[rA*AST + nt*8 + 2*tg] = make_float2(acc[nt][0], acc[nt][1]);
            *(float2*)&sP[rB*AST + nt*8 + 2*tg] = make_float2(acc[nt][2], acc[nt][3]);
        }
        __syncwarp();

        #pragma unroll
        for (int kk = 0; kk < 8; kk++) {
            const int k0 = kk*8;
            float p0 = sP[rA*AST + k0 + tg];
            float p1 = sP[rB*AST + k0 + tg];
            float p2 = sP[rA*AST + k0 + tg + 4];
            float p3 = sP[rB*AST + k0 + tg + 4];
            unsigned int ah0 = f2tf32(p0), ah1 = f2tf32(p1);
            unsigned int ah2 = f2tf32(p2), ah3 = f2tf32(p3);
            unsigned int al0 = f2tf32(p0 - __uint_as_float(ah0));
            unsigned int al1 = f2tf32(p1 - __uint_as_float(ah1));
            unsigned int al2 = f2tf32(p2 - __uint_as_float(ah2));
            unsigned int al3 = f2tf32(p3 - __uint_as_float(ah3));
            #pragma unroll
            for (int nt = 0; nt < 8; nt++) {
                const int n = nt*8 + g;
                float b0f = sV[(k0 + tg)*AST + n];
                float b1f = sV[(k0 + tg + 4)*AST + n];
                unsigned int bh0 = f2tf32(b0f), bh1 = f2tf32(b1f);
                unsigned int bl0 = f2tf32(b0f - __uint_as_float(bh0));
                unsigned int bl1 = f2tf32(b1f - __uint_as_float(bh1));
                mma_tf32(O[nt], ah0, ah1, ah2, ah3, bh0, bh1);
                mma_tf32(O[nt], ah0, ah1, ah2, ah3, bl0, bl1);
                mma_tf32(O[nt], al0, al1, al2, al3, bh0, bh1);
            }
        }
    }

    const int slot = (int)(bh*NCHUNK) + cb + chunk;
    float* pO = g_pO + (size_t)slot*64*64;
    #pragma unroll
    for (int nt = 0; nt < 8; nt++) {
        *(float2*)&pO[rA*64 + nt*8 + 2*tg] = make_float2(O[nt][0], O[nt][1]);
        *(float2*)&pO[rB*64 + nt*8 + 2*tg] = make_float2(O[nt][2], O[nt][3]);
    }
    if (tg == 0) {
        g_pm[slot*64 + rA] = mA;  g_pl[slot*64 + rA] = lA;
        g_pm[slot*64 + rB] = mB;  g_pl[slot*64 + rB] = lB;
    }
}

// ---------------- split-KV reduce: merge partials, mask, scramble --------------
__global__ void __launch_bounds__(128) reduce_kernel() {
    const int it = blockIdx.x, h = blockIdx.y, b = blockIdx.z;
    int base = 0;
    for (int k = 0; k < it; k++) base += (k + 4) >> 2;
    const int nc = (it + 4) >> 2;
    const int slot0 = (b*HEADS_N + h)*NCHUNK + base;
    const int tid = threadIdx.x;
    const int row = tid >> 1;
    const int half = (tid & 1)*32;

    float mstar = -1e30f;
    for (int p = 0; p < nc; p++)
        mstar = fmaxf(mstar, g_pm[(slot0 + p)*64 + row]);

    float lstar = 0.f;
    float Oa[32];
    #pragma unroll
    for (int d = 0; d < 32; d++) Oa[d] = 0.f;

    for (int p = 0; p < nc; p++) {
        const float f = __expf(g_pm[(slot0 + p)*64 + row] - mstar);
        lstar += g_pl[(slot0 + p)*64 + row] * f;
        const float* po = g_pO + ((size_t)(slot0 + p)*64 + row)*64 + half;
        #pragma unroll
        for (int d4 = 0; d4 < 8; d4++) {
            float4 v = *(const float4*)&po[d4*4];
            Oa[d4*4 + 0] += f*v.x;
            Oa[d4*4 + 1] += f*v.y;
            Oa[d4*4 + 2] += f*v.z;
            Oa[d4*4 + 3] += f*v.w;
        }
    }

    const int i = it*64 + row;
    const unsigned int mk = g_pmask[b*TLEN + i];
    const float inv = 1.f / lstar;
    float* dst = &g_attn[((size_t)(b*TLEN) + h*256 + (i >> 3))*EDIM
                         + ((i & 7) << 6) + half];
    if (mk != 0u) {
        #pragma unroll
        for (int d = 0; d < 32; d++) dst[d] = Oa[d]*inv;
    } else {
        const float* vm = &g_vmean[(b*HEADS_N + h)*SDIM + half];
        #pragma unroll
        for (int d = 0; d < 32; d++) dst[d] = vm[d];
    }
}

// ---------------- output projection: out = attnS @ Wo^T + bo -------------------
__global__ void outproj_kernel(const float* __restrict__ Wo,
                               const float* __restrict__ bo,
                               float* __restrict__ out) {
    __shared__ float sAt[64*64];
    __shared__ float sBt[64*64];
    const int m0 = blockIdx.x * 64;
    const int n0 = blockIdx.y * 64;
    const int tid = threadIdx.x;
    const int tx = tid & 15;
    const int ty = tid >> 4;

    float acc[4][4];
    #pragma unroll
    for (int r = 0; r < 4; r++)
        #pragma unroll
        for (int c = 0; c < 4; c++) acc[r][c] = 0.f;

    for (int kc = 0; kc < EDIM; kc += 64) {
        __syncthreads();
        for (int k = tid; k < 1024; k += 256) {
            int rr = k >> 4, c4 = k & 15;
            float4 a = *(const float4*)&g_attn[(size_t)(m0 + rr)*EDIM + kc + c4*4];
            int basea = c4*4*64 + (((rr >> 2) ^ c4) & 15)*4 + (rr & 3);
            sAt[basea]       = a.x;
            sAt[basea + 64]  = a.y;
            sAt[basea + 128] = a.z;
            sAt[basea + 192] = a.w;
            float4 bw = *(const float4*)&Wo[(size_t)(n0 + rr)*EDIM + kc + c4*4];
            sBt[basea]       = bw.x;
            sBt[basea + 64]  = bw.y;
            sBt[basea + 128] = bw.z;
            sBt[basea + 192] = bw.w;
        }
        __syncthreads();
        #pragma unroll 4
        for (int s4 = 0; s4 < 16; s4++) {
            const int ma = ((ty ^ s4) & 15)*4;
            const int mb = ((tx ^ s4) & 15)*4;
            #pragma unroll
            for (int j = 0; j < 4; j++) {
                const int s = s4*4 + j;
                float4 a4 = *(const float4*)&sAt[s*64 + ma];
                float4 b4 = *(const float4*)&sBt[s*64 + mb];
                float ra[4] = {a4.x, a4.y, a4.z, a4.w};
                float rb[4] = {b4.x, b4.y, b4.z, b4.w};
                #pragma unroll
                for (int r = 0; r < 4; r++)
                    #pragma unroll
                    for (int c = 0; c < 4; c++)
                        acc[r][c] = fmaf(ra[r], rb[c], acc[r][c]);
            }
        }
    }

    #pragma unroll
    for (int r = 0; r < 4; r++)
        #pragma unroll
        for (int c = 0; c < 4; c++)
            out[(size_t)(m0 + ty*4 + r)*EDIM + n0 + tx*4 + c] =
                acc[r][c] + bo[n0 + tx*4 + c];
}

// ---------------- launch ----------------
extern "C" void kernel_launch(void* const* d_in, const int* in_sizes, int n_in,
                              void* d_out, int out_size) {
    int idx_x = -1, idx_Er = -1, idx_Wo = -1, idx_bo = -1;
    int cand[8]; int ncand = 0;
    for (int scale = 1; scale <= 4; scale *= 4) {
        idx_x = idx_Er = idx_Wo = idx_bo = -1; ncand = 0;
        for (int i = 0; i < n_in; i++) {
            long long s = in_sizes[i];
            if      (s == (long long)BATCH*TLEN*EDIM*scale)   idx_x  = i;
            else if (s == (long long)HEADS_N*TLEN*SDIM*scale) idx_Er = i;
            else if (s == (long long)EDIM*EDIM*scale)         idx_Wo = i;
            else if (s == (long long)EDIM*scale)              idx_bo = i;
            else if (s == (long long)SDIM*SDIM*scale && ncand < 8) cand[ncand++] = i;
        }
        if (idx_x >= 0 && idx_Er >= 0 && idx_Wo >= 0 && idx_bo >= 0 && ncand == 4)
            break;
    }
    if (!(idx_x >= 0 && idx_Er >= 0 && idx_Wo >= 0 && idx_bo >= 0 && ncand == 4)) {
        int wi = (n_in >= 9) ? 3 : 2;
        idx_x = 0; cand[0] = 1; cand[1] = wi; cand[2] = wi + 1; cand[3] = wi + 2;
        idx_Er = wi + 3; idx_Wo = wi + 4; idx_bo = wi + 5; ncand = 4;
    }

    const float* x  = (const float*)d_in[idx_x];
    const float* Er = (const float*)d_in[idx_Er];
    const float* Wo = (const float*)d_in[idx_Wo];
    const float* bo = (const float*)d_in[idx_bo];
    float* out = (float*)d_out;

    const int PROJ_SMEM = (192*64 + 128*64) * (int)sizeof(float);   // 81920 B
    const int ATTN_SMEM = (4*64*AST) * (int)sizeof(float);          // 69632 B
    const int RG_SMEM   = (4*64*68) * (int)sizeof(float);           // 69632 B
    cudaFuncSetAttribute(proj_kernel, cudaFuncAttributeMaxDynamicSharedMemorySize, PROJ_SMEM);
    cudaFuncSetAttribute(attn_part_kernel, cudaFuncAttributeMaxDynamicSharedMemorySize, ATTN_SMEM);
    cudaFuncSetAttribute(relgemm_kernel, cudaFuncAttributeMaxDynamicSharedMemorySize, RG_SMEM);

    select_inputs<<<1, 256>>>((const float*)d_in[cand[0]], (const float*)d_in[cand[1]],
                              (const float*)d_in[cand[2]], (const float*)d_in[cand[3]],
                              (idx_x == 0) ? 1 : 0);
    proj_kernel<<<dim3(TLEN/128, HEADS_N, BATCH), 256, PROJ_SMEM>>>(x);
    relgemm_kernel<<<dim3(NCHUNK + 1, HEADS_N, BATCH), 256, RG_SMEM>>>(Er);
    attn_part_kernel<<<dim3(NCHUNK, HEADS_N, BATCH), 128, ATTN_SMEM>>>();
    reduce_kernel<<<dim3(TLEN/64, HEADS_N, BATCH), 128>>>();
    outproj_kernel<<<dim3((BATCH*TLEN)/64, EDIM/64), 256>>>(Wo, bo, out);
}

// round 13
// speedup vs baseline: 1.5851x; 1.2590x over previous
#include <cuda_runtime.h>
#include <math.h>

#define TLEN    2048
#define HEADS_N 8
#define BATCH   2
#define SDIM    64
#define EDIM    512
#define QE_BH   2162688   // 4096 * 528 floats per (b,h)
#define NCHUNK  144       // sum over it of ceil((it+1)/4)

// ---------------- scratch + resolved input pointers (device-resident) ----------
__device__ float g_q[BATCH*HEADS_N*TLEN*SDIM];
__device__ float g_k[BATCH*HEADS_N*TLEN*SDIM];
__device__ float g_v[BATCH*HEADS_N*TLEN*SDIM];
__device__ float g_vmean[BATCH*HEADS_N*SDIM];
__device__ float g_attn[BATCH*TLEN*EDIM];
__device__ float g_qe[BATCH*HEADS_N*QE_BH];   // triangular-packed QE bands
__device__ float g_pO[(size_t)BATCH*HEADS_N*NCHUNK*64*64];   // split-KV partials
__device__ float g_pm[BATCH*HEADS_N*NCHUNK*64];
__device__ float g_pl[BATCH*HEADS_N*NCHUNK*64];

__device__ const float*        g_pWq;
__device__ const float*        g_pWk;
__device__ const float*        g_pWv;
__device__ const unsigned int* g_pmask;

// ---------------- tf32 helpers ----------------
__device__ __forceinline__ unsigned int f2tf32(float x) {
    unsigned int r;
    asm("cvt.rna.tf32.f32 %0, %1;" : "=r"(r) : "f"(x));
    return r;
}
__device__ __forceinline__ void mma_tf32(float d[4],
        unsigned int a0, unsigned int a1, unsigned int a2, unsigned int a3,
        unsigned int b0, unsigned int b1) {
    asm("mma.sync.aligned.m16n8k8.row.col.f32.tf32.tf32.f32 "
        "{%0,%1,%2,%3}, {%4,%5,%6,%7}, {%8,%9}, {%0,%1,%2,%3};"
        : "+f"(d[0]), "+f"(d[1]), "+f"(d[2]), "+f"(d[3])
        : "r"(a0), "r"(a1), "r"(a2), "r"(a3), "r"(b0), "r"(b1));
}

// ---------------- prologue: content-based identification of mask ---------------
__global__ void select_inputs(const float* c0, const float* c1,
                              const float* c2, const float* c3, int x_first) {
    __shared__ int bad[4];
    const float* cand[4] = {c0, c1, c2, c3};
    if (threadIdx.x < 4) bad[threadIdx.x] = 0;
    __syncthreads();
    for (int j = 0; j < 4; j++) {
        const unsigned int* p = (const unsigned int*)cand[j];
        int b = 0;
        for (int i = threadIdx.x; i < SDIM*SDIM; i += blockDim.x) {
            unsigned int v = p[i];
            if (v != 0u && v != 1u && v != 0x3F800000u) { b = 1; break; }
        }
        if (b) atomicOr(&bad[j], 1);
    }
    __syncthreads();
    if (threadIdx.x == 0) {
        int mi = -1;
        for (int j = 0; j < 4; j++) if (!bad[j]) { mi = j; break; }
        if (mi < 0) mi = x_first ? 0 : 3;
        const float* rest[3]; int n = 0;
        for (int j = 0; j < 4; j++) if (j != mi) rest[n++] = cand[j];
        g_pmask = (const unsigned int*)cand[mi];
        if (x_first) { g_pWq = rest[0]; g_pWk = rest[1]; g_pWv = rest[2]; }
        else         { g_pWk = rest[0]; g_pWq = rest[1]; g_pWv = rest[2]; }
    }
}

// ---------------- QKV projection via tf32 3x mma ----------------
// grid: (TLEN/128, 3*H, B), 256 threads = 8 warps, each warp 16 t-rows x 64 o.
// q/k/v[bh][t][o] = sum_i x[b,t,h*64+i] * W[o,i] -> A=x rows, B=W rows (row.col)
__global__ void __launch_bounds__(256) proj_kernel(const float* __restrict__ x) {
    extern __shared__ float sm[];
    float* sX = sm;              // [row=128][k=64] fp32, stride 68
    float* sWh = sX + 128*68;    // [o=64][k] hi
    float* sWl = sWh + 64*68;    // lo

    const int m0 = blockIdx.x * 128;
    const int h  = blockIdx.y / 3;
    const int mm = blockIdx.y % 3;
    const int b  = blockIdx.z;
    const int tid = threadIdx.x;
    const float* W = (mm == 0) ? g_pWq : (mm == 1) ? g_pWk : g_pWv;
    float* dst = (mm == 0) ? g_q : (mm == 1) ? g_k : g_v;

    for (int k = tid; k < 2048; k += 256) {     // stage x tile (fp32)
        int row = k >> 4, i4 = (k & 15)*4;
        *(float4*)&sX[row*68 + i4] =
            *(const float4*)&x[(size_t)(b*TLEN + m0 + row)*EDIM + h*SDIM + i4];
    }
    for (int k = tid; k < 1024; k += 256) {     // stage W hi/lo
        int row = k >> 4, i4 = (k & 15)*4;
        float4 f = *(const float4*)&W[row*SDIM + i4];
        float hx = __uint_as_float(f2tf32(f.x));
        float hy = __uint_as_float(f2tf32(f.y));
        float hz = __uint_as_float(f2tf32(f.z));
        float hw = __uint_as_float(f2tf32(f.w));
        *(float4*)&sWh[row*68 + i4] = make_float4(hx, hy, hz, hw);
        *(float4*)&sWl[row*68 + i4] = make_float4(
            __uint_as_float(f2tf32(f.x - hx)), __uint_as_float(f2tf32(f.y - hy)),
            __uint_as_float(f2tf32(f.z - hz)), __uint_as_float(f2tf32(f.w - hw)));
    }
    __syncthreads();

    const int w = tid >> 5, lane = tid & 31;
    const int g = lane >> 2, tg = lane & 3;
    const int mr = w*16 + g;

    float acc[8][4];
    #pragma unroll
    for (int nt = 0; nt < 8; nt++)
        #pragma unroll
        for (int i = 0; i < 4; i++) acc[nt][i] = 0.f;

    #pragma unroll
    for (int kk = 0; kk < 8; kk++) {
        const int k0 = kk*8;
        float q0 = sX[mr*68 + k0 + tg];
        float q1 = sX[(mr + 8)*68 + k0 + tg];
        float q2 = sX[mr*68 + k0 + tg + 4];
        float q3 = sX[(mr + 8)*68 + k0 + tg + 4];
        unsigned int ah0 = f2tf32(q0), ah1 = f2tf32(q1);
        unsigned int ah2 = f2tf32(q2), ah3 = f2tf32(q3);
        unsigned int al0 = f2tf32(q0 - __uint_as_float(ah0));
        unsigned int al1 = f2tf32(q1 - __uint_as_float(ah1));
        unsigned int al2 = f2tf32(q2 - __uint_as_float(ah2));
        unsigned int al3 = f2tf32(q3 - __uint_as_float(ah3));
        #pragma unroll
        for (int nt = 0; nt < 8; nt++) {
            const int n = nt*8 + g;
            unsigned int bh0 = __float_as_uint(sWh[n*68 + k0 + tg]);
            unsigned int bh1 = __float_as_uint(sWh[n*68 + k0 + tg + 4]);
            unsigned int bl0 = __float_as_uint(sWl[n*68 + k0 + tg]);
            unsigned int bl1 = __float_as_uint(sWl[n*68 + k0 + tg + 4]);
            mma_tf32(acc[nt], ah0, ah1, ah2, ah3, bh0, bh1);
            mma_tf32(acc[nt], ah0, ah1, ah2, ah3, bl0, bl1);
            mma_tf32(acc[nt], al0, al1, al2, al3, bh0, bh1);
        }
    }

    const size_t bh = (size_t)(b*HEADS_N + h);
    #pragma unroll
    for (int nt = 0; nt < 8; nt++) {
        const int col = nt*8 + 2*tg;
        *(float2*)&dst[(bh*TLEN + m0 + mr)*SDIM + col] =
            make_float2(acc[nt][0], acc[nt][1]);
        *(float2*)&dst[(bh*TLEN + m0 + mr + 8)*SDIM + col] =
            make_float2(acc[nt][2], acc[nt][3]);
    }
}

// ---------------- rel-pos GEMM v2: chunked, natural-layout B ----------------
__global__ void __launch_bounds__(256) relgemm_kernel(const float* __restrict__ Er) {
    extern __shared__ float sm[];
    const int tid = threadIdx.x;
    const int h = blockIdx.y, b = blockIdx.z;

    if (blockIdx.x == NCHUNK) {   // fused V-mean for (b,h)
        const int bh = b*HEADS_N + h;
        const int d = tid & 63, sub = tid >> 6;
        float a = 0.f;
        for (int l = sub; l < TLEN; l += 4)
            a += g_v[((size_t)bh*TLEN + l)*SDIM + d];
        sm[sub*64 + d] = a;
        __syncthreads();
        if (sub == 0)
            g_vmean[bh*SDIM + d] =
                (sm[d] + sm[64 + d] + sm[128 + d] + sm[192 + d]) * (1.f/(float)TLEN);
        return;
    }

    float* Qh = sm;              // [m=64][k] stride 68
    float* Ql = Qh + 64*68;
    float* Eh = Ql + 64*68;      // [n=o][k=s] natural rows, stride 68
    float* El = Eh + 64*68;

    const int x = (int)blockIdx.x;
    int it = 31, cb = 0;
    {
        int base = 0;
        for (int k = 0; k < 32; k++) {
            int nch = (k + 4) >> 2;
            if (x < base + nch) { it = k; cb = base; break; }
            base += nch;
        }
    }
    const int chunk = x - cb;
    const int osta = chunk*4;
    const int oend = min(osta + 4, it + 1);
    const int i0 = it * 64;

    const float* gq = g_q + (size_t)(b*HEADS_N + h)*TLEN*SDIM + (size_t)i0*SDIM;
    const float* ge = Er + (size_t)h*TLEN*SDIM;

    #pragma unroll
    for (int kk = 0; kk < 4; kk++) {
        int k = kk*256 + tid;
        int m = k >> 4, s4 = (k & 15)*4;
        float4 f = *(const float4*)&gq[m*SDIM + s4];
        float hx = __uint_as_float(f2tf32(f.x));
        float hy = __uint_as_float(f2tf32(f.y));
        float hz = __uint_as_float(f2tf32(f.z));
        float hw = __uint_as_float(f2tf32(f.w));
        *(float4*)&Qh[m*68 + s4] = make_float4(hx, hy, hz, hw);
        *(float4*)&Ql[m*68 + s4] = make_float4(
            __uint_as_float(f2tf32(f.x - hx)), __uint_as_float(f2tf32(f.y - hy)),
            __uint_as_float(f2tf32(f.z - hz)), __uint_as_float(f2tf32(f.w - hw)));
    }

    const int w = tid >> 5, lane = tid & 31;
    const int g = lane >> 2, tg = lane & 3;
    const int mr = (w & 3)*16 + g;
    const int nb = (w >> 2)*32;

    const int W = 64*(it + 1);
    float* qb = g_qe + (size_t)(b*HEADS_N + h)*QE_BH + (size_t)4096*(it*(it + 1)/2);

    for (int oc = osta; oc < oend; oc++) {
        const int j0 = TLEN - 64 - i0 + oc*64;
        __syncthreads();
        #pragma unroll
        for (int kk = 0; kk < 4; kk++) {
            int k = kk*256 + tid;
            int o = k >> 4, s4 = (k & 15)*4;
            float4 f = *(const float4*)&ge[(size_t)(j0 + o)*SDIM + s4];
            float hx = __uint_as_float(f2tf32(f.x));
            float hy = __uint_as_float(f2tf32(f.y));
            float hz = __uint_as_float(f2tf32(f.z));
            float hw = __uint_as_float(f2tf32(f.w));
            *(float4*)&Eh[o*68 + s4] = make_float4(hx, hy, hz, hw);
            *(float4*)&El[o*68 + s4] = make_float4(
                __uint_as_float(f2tf32(f.x - hx)), __uint_as_float(f2tf32(f.y - hy)),
                __uint_as_float(f2tf32(f.z - hz)), __uint_as_float(f2tf32(f.w - hw)));
        }
        __syncthreads();

        float d[4][4];
        #pragma unroll
        for (int nt = 0; nt < 4; nt++)
            #pragma unroll
            for (int i = 0; i < 4; i++) d[nt][i] = 0.f;

        #pragma unroll
        for (int kk = 0; kk < 8; kk++) {
            const int k0 = kk*8;
            unsigned int ah0 = __float_as_uint(Qh[mr*68 + k0 + tg]);
            unsigned int ah1 = __float_as_uint(Qh[(mr + 8)*68 + k0 + tg]);
            unsigned int ah2 = __float_as_uint(Qh[mr*68 + k0 + tg + 4]);
            unsigned int ah3 = __float_as_uint(Qh[(mr + 8)*68 + k0 + tg + 4]);
            unsigned int al0 = __float_as_uint(Ql[mr*68 + k0 + tg]);
            unsigned int al1 = __float_as_uint(Ql[(mr + 8)*68 + k0 + tg]);
            unsigned int al2 = __float_as_uint(Ql[mr*68 + k0 + tg + 4]);
            unsigned int al3 = __float_as_uint(Ql[(mr + 8)*68 + k0 + tg + 4]);
            #pragma unroll
            for (int nt = 0; nt < 4; nt++) {
                const int n = nb + nt*8 + g;
                unsigned int bh0 = __float_as_uint(Eh[n*68 + k0 + tg]);
                unsigned int bh1 = __float_as_uint(Eh[n*68 + k0 + tg + 4]);
                unsigned int bl0 = __float_as_uint(El[n*68 + k0 + tg]);
                unsigned int bl1 = __float_as_uint(El[n*68 + k0 + tg + 4]);
                mma_tf32(d[nt], ah0, ah1, ah2, ah3, bh0, bh1);
                mma_tf32(d[nt], ah0, ah1, ah2, ah3, bl0, bl1);
                mma_tf32(d[nt], al0, al1, al2, al3, bh0, bh1);
            }
        }

        const int colb = oc*64 + nb;
        #pragma unroll
        for (int nt = 0; nt < 4; nt++) {
            const int col = colb + nt*8 + 2*tg;
            *(float2*)&qb[(size_t)mr*W + col]       = make_float2(d[nt][0], d[nt][1]);
            *(float2*)&qb[(size_t)(mr + 8)*W + col] = make_float2(d[nt][2], d[nt][3]);
        }
    }
}

// ---------------- split-KV tensor-core flash attention (partials) ---------------
// QK uses 2-term split (Qhi+Qlo)*Khi — dropped q*K_lo errs ~1.7e-4 abs on scores
// (QK term sigma ~0.35; QE term is fp32-grade). PV keeps 3-term.
#define AST 68   // 68 mod 32 == 4 -> all fragment LDS conflict-free
__global__ void __launch_bounds__(128, 3) attn_part_kernel() {
    extern __shared__ float sm[];
    float* sQ = sm;              // [i][s]  64 x AST
    float* sK = sQ + 64*AST;     // [c][s]  (pre-scaled)
    float* sV = sK + 64*AST;     // [lc][d]
    float* sP = sV + 64*AST;     // [i][lc]

    const int x = NCHUNK - 1 - (int)blockIdx.x;   // heavy i-tiles first
    int it = 31, cb = 0;
    {
        int base = 0;
        for (int k = 0; k < 32; k++) {
            int nch = (k + 4) >> 2;
            if (x < base + nch) { it = k; cb = base; break; }
            base += nch;
        }
    }
    const int chunk = x - cb;
    const int csta = chunk*4;
    const int cend = min(csta + 4, it + 1);
    const int i0 = it * 64;

    const int h  = blockIdx.y;
    const int b  = blockIdx.z;
    const int tid = threadIdx.x;
    const int w = tid >> 5, lane = tid & 31;
    const int g = lane >> 2, tg = lane & 3;
    const int rA = w*16 + g, rB = rA + 8;
    const float scale2 = 0.04419417382415922f;   // 512^-0.5

    const size_t bh = (size_t)(b*HEADS_N + h);
    const float* gq = g_q + bh*TLEN*SDIM;
    const float* gk = g_k + bh*TLEN*SDIM;
    const float* gv = g_v + bh*TLEN*SDIM;

    const int Wqe = 64*(it + 1);
    const float* qeb = g_qe + bh*QE_BH + (size_t)4096*(it*(it + 1)/2);
    const int omax = i0 + 63;

    for (int k = tid; k < 1024; k += 128) {
        int li = k >> 4, s4 = (k & 15)*4;
        *(float4*)&sQ[li*AST + s4] =
            *(const float4*)&gq[(size_t)(i0 + li)*SDIM + s4];
    }

    float mA = -1e30f, mB = -1e30f, lA = 0.f, lB = 0.f;
    float O[8][4];
    #pragma unroll
    for (int nt = 0; nt < 8; nt++)
        #pragma unroll
        for (int i = 0; i < 4; i++) O[nt][i] = 0.f;

    for (int ct = csta; ct < cend; ct++) {
        const int c0 = ct * 64;
        __syncthreads();
        for (int k = tid; k < 1024; k += 128) {
            int li = k >> 4, s4 = (k & 15)*4;
            float4 f = *(const float4*)&gk[(size_t)(c0 + li)*SDIM + s4];
            f.x *= scale2; f.y *= scale2; f.z *= scale2; f.w *= scale2;
            *(float4*)&sK[li*AST + s4] = f;
            *(float4*)&sV[li*AST + s4] =
                *(const float4*)&gv[(size_t)(c0 + li)*SDIM + s4];
        }
        __syncthreads();

        float acc[8][4];
        #pragma unroll
        for (int nt = 0; nt < 8; nt++)
            #pragma unroll
            for (int i = 0; i < 4; i++) acc[nt][i] = 0.f;

        // ---- S = Q K^T : 2-term (Qhi + Qlo) * Khi ----
        #pragma unroll
        for (int kk = 0; kk < 8; kk++) {
            const int k0 = kk*8;
            float q0 = sQ[rA*AST + k0 + tg];
            float q1 = sQ[rB*AST + k0 + tg];
            float q2 = sQ[rA*AST + k0 + tg + 4];
            float q3 = sQ[rB*AST + k0 + tg + 4];
            unsigned int ah0 = f2tf32(q0), ah1 = f2tf32(q1);
            unsigned int ah2 = f2tf32(q2), ah3 = f2tf32(q3);
            unsigned int al0 = f2tf32(q0 - __uint_as_float(ah0));
            unsigned int al1 = f2tf32(q1 - __uint_as_float(ah1));
            unsigned int al2 = f2tf32(q2 - __uint_as_float(ah2));
            unsigned int al3 = f2tf32(q3 - __uint_as_float(ah3));
            #pragma unroll
            for (int nt = 0; nt < 8; nt++) {
                const int n = nt*8 + g;
                unsigned int bh0 = f2tf32(sK[n*AST + k0 + tg]);
                unsigned int bh1 = f2tf32(sK[n*AST + k0 + tg + 4]);
                mma_tf32(acc[nt], ah0, ah1, ah2, ah3, bh0, bh1);
                mma_tf32(acc[nt], al0, al1, al2, al3, bh0, bh1);
            }
        }

        #pragma unroll
        for (int nt = 0; nt < 8; nt++) {
            const int cl = nt*8 + 2*tg;
            const int oA = 63 - rA + c0 + cl;
            const int oB = 63 - rB + c0 + cl;
            if (oA     <= omax) acc[nt][0] += __ldg(qeb + (size_t)rA*Wqe + oA);
            if (oA + 1 <= omax) acc[nt][1] += __ldg(qeb + (size_t)rA*Wqe + oA + 1);
            if (oB     <= omax) acc[nt][2] += __ldg(qeb + (size_t)rB*Wqe + oB);
            if (oB + 1 <= omax) acc[nt][3] += __ldg(qeb + (size_t)rB*Wqe + oB + 1);
            if (ct == it) {
                if (cl     > rA) acc[nt][0] = -1e30f;
                if (cl + 1 > rA) acc[nt][1] = -1e30f;
                if (cl     > rB) acc[nt][2] = -1e30f;
                if (cl + 1 > rB) acc[nt][3] = -1e30f;
            }
        }

        float mxA = -1e30f, mxB = -1e30f;
        #pragma unroll
        for (int nt = 0; nt < 8; nt++) {
            mxA = fmaxf(mxA, fmaxf(acc[nt][0], acc[nt][1]));
            mxB = fmaxf(mxB, fmaxf(acc[nt][2], acc[nt][3]));
        }
        mxA = fmaxf(mxA, __shfl_xor_sync(0xffffffffu, mxA, 1));
        mxA = fmaxf(mxA, __shfl_xor_sync(0xffffffffu, mxA, 2));
        mxB = fmaxf(mxB, __shfl_xor_sync(0xffffffffu, mxB, 1));
        mxB = fmaxf(mxB, __shfl_xor_sync(0xffffffffu, mxB, 2));
        const float mnA = fmaxf(mA, mxA), mnB = fmaxf(mB, mxB);
        const float cA = __expf(mA - mnA), cB = __expf(mB - mnB);
        float sA = 0.f, sB = 0.f;
        #pragma unroll
        for (int nt = 0; nt < 8; nt++) {
            acc[nt][0] = __expf(acc[nt][0] - mnA);
            acc[nt][1] = __expf(acc[nt][1] - mnA);
            acc[nt][2] = __expf(acc[nt][2] - mnB);
            acc[nt][3] = __expf(acc[nt][3] - mnB);
            sA += acc[nt][0] + acc[nt][1];
            sB += acc[nt][2] + acc[nt][3];
        }
        sA += __shfl_xor_sync(0xffffffffu, sA, 1);
        sA += __shfl_xor_sync(0xffffffffu, sA, 2);
        sB += __shfl_xor_sync(0xffffffffu, sB, 1);
        sB += __shfl_xor_sync(0xffffffffu, sB, 2);
        lA = lA*cA + sA;  mA = mnA;
        lB = lB*cB + sB;  mB = mnB;
        #pragma unroll
        for (int nt = 0; nt < 8; nt++) {
            O[nt][0] *= cA; O[nt][1] *= cA;
            O[nt][2] *= cB; O[nt][3] *= cB;
        }

        #pragma unroll
        for (int nt = 0; nt < 8; nt++) {
            *(float2*)&sP[rA*AST + nt*8 + 2*tg] = make_float2(acc[nt][0], acc[nt][1]);
            *(float2*)&sP[rB*AST + nt*8 + 2*tg] = make_float2(acc[nt][2], acc[nt][3]);
        }
        __syncwarp();

        // ---- O += P V : 3-term ----
        #pragma unroll
        for (int kk = 0; kk < 8; kk++) {
            const int k0 = kk*8;
            float p0 = sP[rA*AST + k0 + tg];
            float p1 = sP[rB*AST + k0 + tg];
            float p2 = sP[rA*AST + k0 + tg + 4];
            float p3 = sP[rB*AST + k0 + tg + 4];
            unsigned int ah0 = f2tf32(p0), ah1 = f2tf32(p1);
            unsigned int ah2 = f2tf32(p2), ah3 = f2tf32(p3);
            unsigned int al0 = f2tf32(p0 - __uint_as_float(ah0));
            unsigned int al1 = f2tf32(p1 - __uint_as_float(ah1));
            unsigned int al2 = f2tf32(p2 - __uint_as_float(ah2));
            unsigned int al3 = f2tf32(p3 - __uint_as_float(ah3));
            #pragma unroll
            for (int nt = 0; nt < 8; nt++) {
                const int n = nt*8 + g;
                float b0f = sV[(k0 + tg)*AST + n];
                float b1f = sV[(k0 + tg + 4)*AST + n];
                unsigned int bh0 = f2tf32(b0f), bh1 = f2tf32(b1f);
                unsigned int bl0 = f2tf32(b0f - __uint_as_float(bh0));
                unsigned int bl1 = f2tf32(b1f - __uint_as_float(bh1));
                mma_tf32(O[nt], ah0, ah1, ah2, ah3, bh0, bh1);
                mma_tf32(O[nt], ah0, ah1, ah2, ah3, bl0, bl1);
                mma_tf32(O[nt], al0, al1, al2, al3, bh0, bh1);
            }
        }
    }

    const int slot = (int)(bh*NCHUNK) + cb + chunk;
    float* pO = g_pO + (size_t)slot*64*64;
    #pragma unroll
    for (int nt = 0; nt < 8; nt++) {
        *(float2*)&pO[rA*64 + nt*8 + 2*tg] = make_float2(O[nt][0], O[nt][1]);
        *(float2*)&pO[rB*64 + nt*8 + 2*tg] = make_float2(O[nt][2], O[nt][3]);
    }
    if (tg == 0) {
        g_pm[slot*64 + rA] = mA;  g_pl[slot*64 + rA] = lA;
        g_pm[slot*64 + rB] = mB;  g_pl[slot*64 + rB] = lB;
    }
}

// ---------------- split-KV reduce: merge partials, mask, scramble --------------
__global__ void __launch_bounds__(128) reduce_kernel() {
    const int it = blockIdx.x, h = blockIdx.y, b = blockIdx.z;
    int base = 0;
    for (int k = 0; k < it; k++) base += (k + 4) >> 2;
    const int nc = (it + 4) >> 2;
    const int slot0 = (b*HEADS_N + h)*NCHUNK + base;
    const int tid = threadIdx.x;
    const int row = tid >> 1;
    const int half = (tid & 1)*32;

    float mstar = -1e30f;
    for (int p = 0; p < nc; p++)
        mstar = fmaxf(mstar, g_pm[(slot0 + p)*64 + row]);

    float lstar = 0.f;
    float Oa[32];
    #pragma unroll
    for (int d = 0; d < 32; d++) Oa[d] = 0.f;

    for (int p = 0; p < nc; p++) {
        const float f = __expf(g_pm[(slot0 + p)*64 + row] - mstar);
        lstar += g_pl[(slot0 + p)*64 + row] * f;
        const float* po = g_pO + ((size_t)(slot0 + p)*64 + row)*64 + half;
        #pragma unroll
        for (int d4 = 0; d4 < 8; d4++) {
            float4 v = *(const float4*)&po[d4*4];
            Oa[d4*4 + 0] += f*v.x;
            Oa[d4*4 + 1] += f*v.y;
            Oa[d4*4 + 2] += f*v.z;
            Oa[d4*4 + 3] += f*v.w;
        }
    }

    const int i = it*64 + row;
    const unsigned int mk = g_pmask[b*TLEN + i];
    const float inv = 1.f / lstar;
    float* dst = &g_attn[((size_t)(b*TLEN) + h*256 + (i >> 3))*EDIM
                         + ((i & 7) << 6) + half];
    if (mk != 0u) {
        #pragma unroll
        for (int d = 0; d < 32; d++) dst[d] = Oa[d]*inv;
    } else {
        const float* vm = &g_vmean[(b*HEADS_N + h)*SDIM + half];
        #pragma unroll
        for (int d = 0; d < 32; d++) dst[d] = vm[d];
    }
}

// ---------------- output projection via tf32 3x mma ----------------------------
// grid: (4096/128, 512/64), 256 threads = 8 warps; warp w owns rows
// [m0+w*16, +16) x 64 cols. out = attnS @ Wo^T + bo (both naturally k-contig).
__global__ void __launch_bounds__(256) outproj_kernel(const float* __restrict__ Wo,
                                                      const float* __restrict__ bo,
                                                      float* __restrict__ out) {
    extern __shared__ float sm[];
    float* sA  = sm;             // [row=128][k=64] fp32, stride 68
    float* sBh = sA + 128*68;    // [n=64][k] hi
    float* sBl = sBh + 64*68;    // lo

    const int m0 = blockIdx.x * 128;
    const int n0 = blockIdx.y * 64;
    const int tid = threadIdx.x;
    const int w = tid >> 5, lane = tid & 31;
    const int g = lane >> 2, tg = lane & 3;
    const int mr = w*16 + g;

    float acc[8][4];
    #pragma unroll
    for (int nt = 0; nt < 8; nt++)
        #pragma unroll
        for (int i = 0; i < 4; i++) acc[nt][i] = 0.f;

    for (int ks = 0; ks < 8; ks++) {
        const int kc = ks*64;
        __syncthreads();
        for (int k = tid; k < 2048; k += 256) {
            int row = k >> 4, i4 = (k & 15)*4;
            *(float4*)&sA[row*68 + i4] =
                *(const float4*)&g_attn[(size_t)(m0 + row)*EDIM + kc + i4];
        }
        for (int k = tid; k < 1024; k += 256) {
            int row = k >> 4, i4 = (k & 15)*4;
            float4 f = *(const float4*)&Wo[(size_t)(n0 + row)*EDIM + kc + i4];
            float hx = __uint_as_float(f2tf32(f.x));
            float hy = __uint_as_float(f2tf32(f.y));
            float hz = __uint_as_float(f2tf32(f.z));
            float hw = __uint_as_float(f2tf32(f.w));
            *(float4*)&sBh[row*68 + i4] = make_float4(hx, hy, hz, hw);
            *(float4*)&sBl[row*68 + i4] = make_float4(
                __uint_as_float(f2tf32(f.x - hx)), __uint_as_float(f2tf32(f.y - hy)),
                __uint_as_float(f2tf32(f.z - hz)), __uint_as_float(f2tf32(f.w - hw)));
        }
        __syncthreads();

        #pragma unroll
        for (int kk = 0; kk < 8; kk++) {
            const int k0 = kk*8;
            float q0 = sA[mr*68 + k0 + tg];
            float q1 = sA[(mr + 8)*68 + k0 + tg];
            float q2 = sA[mr*68 + k0 + tg + 4];
            float q3 = sA[(mr + 8)*68 + k0 + tg + 4];
            unsigned int ah0 = f2tf32(q0), ah1 = f2tf32(q1);
            unsigned int ah2 = f2tf32(q2), ah3 = f2tf32(q3);
            unsigned int al0 = f2tf32(q0 - __uint_as_float(ah0));
            unsigned int al1 = f2tf32(q1 - __uint_as_float(ah1));
            unsigned int al2 = f2tf32(q2 - __uint_as_float(ah2));
            unsigned int al3 = f2tf32(q3 - __uint_as_float(ah3));
            #pragma unroll
            for (int nt = 0; nt < 8; nt++) {
                const int n = nt*8 + g;
                unsigned int bh0 = __float_as_uint(sBh[n*68 + k0 + tg]);
                unsigned int bh1 = __float_as_uint(sBh[n*68 + k0 + tg + 4]);
                unsigned int bl0 = __float_as_uint(sBl[n*68 + k0 + tg]);
                unsigned int bl1 = __float_as_uint(sBl[n*68 + k0 + tg + 4]);
                mma_tf32(acc[nt], ah0, ah1, ah2, ah3, bh0, bh1);
                mma_tf32(acc[nt], ah0, ah1, ah2, ah3, bl0, bl1);
                mma_tf32(acc[nt], al0, al1, al2, al3, bh0, bh1);
            }
        }
    }

    #pragma unroll
    for (int nt = 0; nt < 8; nt++) {
        const int col = n0 + nt*8 + 2*tg;
        const float b0v = bo[col], b1v = bo[col + 1];
        *(float2*)&out[(size_t)(m0 + mr)*EDIM + col] =
            make_float2(acc[nt][0] + b0v, acc[nt][1] + b1v);
        *(float2*)&out[(size_t)(m0 + mr + 8)*EDIM + col] =
            make_float2(acc[nt][2] + b0v, acc[nt][3] + b1v);
    }
}

// ---------------- launch ----------------
extern "C" void kernel_launch(void* const* d_in, const int* in_sizes, int n_in,
                              void* d_out, int out_size) {
    int idx_x = -1, idx_Er = -1, idx_Wo = -1, idx_bo = -1;
    int cand[8]; int ncand = 0;
    for (int scale = 1; scale <= 4; scale *= 4) {
        idx_x = idx_Er = idx_Wo = idx_bo = -1; ncand = 0;
        for (int i = 0; i < n_in; i++) {
            long long s = in_sizes[i];
            if      (s == (long long)BATCH*TLEN*EDIM*scale)   idx_x  = i;
            else if (s == (long long)HEADS_N*TLEN*SDIM*scale) idx_Er = i;
            else if (s == (long long)EDIM*EDIM*scale)         idx_Wo = i;
            else if (s == (long long)EDIM*scale)              idx_bo = i;
            else if (s == (long long)SDIM*SDIM*scale && ncand < 8) cand[ncand++] = i;
        }
        if (idx_x >= 0 && idx_Er >= 0 && idx_Wo >= 0 && idx_bo >= 0 && ncand == 4)
            break;
    }
    if (!(idx_x >= 0 && idx_Er >= 0 && idx_Wo >= 0 && idx_bo >= 0 && ncand == 4)) {
        int wi = (n_in >= 9) ? 3 : 2;
        idx_x = 0; cand[0] = 1; cand[1] = wi; cand[2] = wi + 1; cand[3] = wi + 2;
        idx_Er = wi + 3; idx_Wo = wi + 4; idx_bo = wi + 5; ncand = 4;
    }

    const float* x  = (const float*)d_in[idx_x];
    const float* Er = (const float*)d_in[idx_Er];
    const float* Wo = (const float*)d_in[idx_Wo];
    const float* bo = (const float*)d_in[idx_bo];
    float* out = (float*)d_out;

    const int PROJ_SMEM = (256*68) * (int)sizeof(float);            // 69632 B
    const int ATTN_SMEM = (4*64*AST) * (int)sizeof(float);          // 69632 B
    const int RG_SMEM   = (4*64*68) * (int)sizeof(float);           // 69632 B
    const int OP_SMEM   = (256*68) * (int)sizeof(float);            // 69632 B
    cudaFuncSetAttribute(proj_kernel, cudaFuncAttributeMaxDynamicSharedMemorySize, PROJ_SMEM);
    cudaFuncSetAttribute(attn_part_kernel, cudaFuncAttributeMaxDynamicSharedMemorySize, ATTN_SMEM);
    cudaFuncSetAttribute(relgemm_kernel, cudaFuncAttributeMaxDynamicSharedMemorySize, RG_SMEM);
    cudaFuncSetAttribute(outproj_kernel, cudaFuncAttributeMaxDynamicSharedMemorySize, OP_SMEM);

    select_inputs<<<1, 256>>>((const float*)d_in[cand[0]], (const float*)d_in[cand[1]],
                              (const float*)d_in[cand[2]], (const float*)d_in[cand[3]],
                              (idx_x == 0) ? 1 : 0);
    proj_kernel<<<dim3(TLEN/128, 3*HEADS_N, BATCH), 256, PROJ_SMEM>>>(x);
    relgemm_kernel<<<dim3(NCHUNK + 1, HEADS_N, BATCH), 256, RG_SMEM>>>(Er);
    attn_part_kernel<<<dim3(NCHUNK, HEADS_N, BATCH), 128, ATTN_SMEM>>>();
    reduce_kernel<<<dim3(TLEN/64, HEADS_N, BATCH), 128>>>();
    outproj_kernel<<<dim3((BATCH*TLEN)/128, EDIM/64), 256, OP_SMEM>>>(Wo, bo, out);
}

// round 14
// speedup vs baseline: 1.7102x; 1.0789x over previous
#include <cuda_runtime.h>
#include <math.h>

#define TLEN    2048
#define HEADS_N 8
#define BATCH   2
#define SDIM    64
#define EDIM    512
#define QE_BH   2162688   // 4096 * 528 floats per (b,h)
#define NCHUNK  144       // sum over it of ceil((it+1)/4)

// ---------------- scratch + resolved input pointers (device-resident) ----------
__device__ float g_q[BATCH*HEADS_N*TLEN*SDIM];
__device__ float g_k[BATCH*HEADS_N*TLEN*SDIM];
__device__ float g_v[BATCH*HEADS_N*TLEN*SDIM];
__device__ float g_vmean[BATCH*HEADS_N*SDIM];
__device__ float g_attn[BATCH*TLEN*EDIM];
__device__ float g_qe[BATCH*HEADS_N*QE_BH];   // triangular-packed QE bands
__device__ float g_pO[(size_t)BATCH*HEADS_N*NCHUNK*64*64];   // split-KV partials
__device__ float g_pm[BATCH*HEADS_N*NCHUNK*64];
__device__ float g_pl[BATCH*HEADS_N*NCHUNK*64];

__device__ const float*        g_pWq;
__device__ const float*        g_pWk;
__device__ const float*        g_pWv;
__device__ const unsigned int* g_pmask;

// ---------------- tf32 helpers ----------------
__device__ __forceinline__ unsigned int f2tf32(float x) {
    unsigned int r;
    asm("cvt.rna.tf32.f32 %0, %1;" : "=r"(r) : "f"(x));
    return r;
}
__device__ __forceinline__ float tf32r(float x) {   // round to tf32, as float
    return __uint_as_float(f2tf32(x));
}
__device__ __forceinline__ void mma_tf32(float d[4],
        unsigned int a0, unsigned int a1, unsigned int a2, unsigned int a3,
        unsigned int b0, unsigned int b1) {
    asm("mma.sync.aligned.m16n8k8.row.col.f32.tf32.tf32.f32 "
        "{%0,%1,%2,%3}, {%4,%5,%6,%7}, {%8,%9}, {%0,%1,%2,%3};"
        : "+f"(d[0]), "+f"(d[1]), "+f"(d[2]), "+f"(d[3])
        : "r"(a0), "r"(a1), "r"(a2), "r"(a3), "r"(b0), "r"(b1));
}

// ---------------- prologue: content-based identification of mask ---------------
__global__ void select_inputs(const float* c0, const float* c1,
                              const float* c2, const float* c3, int x_first) {
    __shared__ int bad[4];
    const float* cand[4] = {c0, c1, c2, c3};
    if (threadIdx.x < 4) bad[threadIdx.x] = 0;
    __syncthreads();
    for (int j = 0; j < 4; j++) {
        const unsigned int* p = (const unsigned int*)cand[j];
        int b = 0;
        for (int i = threadIdx.x; i < SDIM*SDIM; i += blockDim.x) {
            unsigned int v = p[i];
            if (v != 0u && v != 1u && v != 0x3F800000u) { b = 1; break; }
        }
        if (b) atomicOr(&bad[j], 1);
    }
    __syncthreads();
    if (threadIdx.x == 0) {
        int mi = -1;
        for (int j = 0; j < 4; j++) if (!bad[j]) { mi = j; break; }
        if (mi < 0) mi = x_first ? 0 : 3;
        const float* rest[3]; int n = 0;
        for (int j = 0; j < 4; j++) if (j != mi) rest[n++] = cand[j];
        g_pmask = (const unsigned int*)cand[mi];
        if (x_first) { g_pWq = rest[0]; g_pWk = rest[1]; g_pWv = rest[2]; }
        else         { g_pWk = rest[0]; g_pWq = rest[1]; g_pWv = rest[2]; }
    }
}

// ---------------- QKV projection via tf32 3x mma ----------------
__global__ void __launch_bounds__(256) proj_kernel(const float* __restrict__ x) {
    extern __shared__ float sm[];
    float* sX = sm;              // [row=128][k=64] fp32, stride 68
    float* sWh = sX + 128*68;    // [o=64][k] hi
    float* sWl = sWh + 64*68;    // lo

    const int m0 = blockIdx.x * 128;
    const int h  = blockIdx.y / 3;
    const int mm = blockIdx.y % 3;
    const int b  = blockIdx.z;
    const int tid = threadIdx.x;
    const float* W = (mm == 0) ? g_pWq : (mm == 1) ? g_pWk : g_pWv;
    float* dst = (mm == 0) ? g_q : (mm == 1) ? g_k : g_v;

    for (int k = tid; k < 2048; k += 256) {
        int row = k >> 4, i4 = (k & 15)*4;
        *(float4*)&sX[row*68 + i4] =
            *(const float4*)&x[(size_t)(b*TLEN + m0 + row)*EDIM + h*SDIM + i4];
    }
    for (int k = tid; k < 1024; k += 256) {
        int row = k >> 4, i4 = (k & 15)*4;
        float4 f = *(const float4*)&W[row*SDIM + i4];
        float hx = tf32r(f.x), hy = tf32r(f.y), hz = tf32r(f.z), hw = tf32r(f.w);
        *(float4*)&sWh[row*68 + i4] = make_float4(hx, hy, hz, hw);
        *(float4*)&sWl[row*68 + i4] = make_float4(
            tf32r(f.x - hx), tf32r(f.y - hy), tf32r(f.z - hz), tf32r(f.w - hw));
    }
    __syncthreads();

    const int w = tid >> 5, lane = tid & 31;
    const int g = lane >> 2, tg = lane & 3;
    const int mr = w*16 + g;

    float acc[8][4];
    #pragma unroll
    for (int nt = 0; nt < 8; nt++)
        #pragma unroll
        for (int i = 0; i < 4; i++) acc[nt][i] = 0.f;

    #pragma unroll
    for (int kk = 0; kk < 8; kk++) {
        const int k0 = kk*8;
        float q0 = sX[mr*68 + k0 + tg];
        float q1 = sX[(mr + 8)*68 + k0 + tg];
        float q2 = sX[mr*68 + k0 + tg + 4];
        float q3 = sX[(mr + 8)*68 + k0 + tg + 4];
        unsigned int ah0 = f2tf32(q0), ah1 = f2tf32(q1);
        unsigned int ah2 = f2tf32(q2), ah3 = f2tf32(q3);
        unsigned int al0 = f2tf32(q0 - __uint_as_float(ah0));
        unsigned int al1 = f2tf32(q1 - __uint_as_float(ah1));
        unsigned int al2 = f2tf32(q2 - __uint_as_float(ah2));
        unsigned int al3 = f2tf32(q3 - __uint_as_float(ah3));
        #pragma unroll
        for (int nt = 0; nt < 8; nt++) {
            const int n = nt*8 + g;
            unsigned int bh0 = __float_as_uint(sWh[n*68 + k0 + tg]);
            unsigned int bh1 = __float_as_uint(sWh[n*68 + k0 + tg + 4]);
            unsigned int bl0 = __float_as_uint(sWl[n*68 + k0 + tg]);
            unsigned int bl1 = __float_as_uint(sWl[n*68 + k0 + tg + 4]);
            mma_tf32(acc[nt], ah0, ah1, ah2, ah3, bh0, bh1);
            mma_tf32(acc[nt], ah0, ah1, ah2, ah3, bl0, bl1);
            mma_tf32(acc[nt], al0, al1, al2, al3, bh0, bh1);
        }
    }

    const size_t bh = (size_t)(b*HEADS_N + h);
    #pragma unroll
    for (int nt = 0; nt < 8; nt++) {
        const int col = nt*8 + 2*tg;
        *(float2*)&dst[(bh*TLEN + m0 + mr)*SDIM + col] =
            make_float2(acc[nt][0], acc[nt][1]);
        *(float2*)&dst[(bh*TLEN + m0 + mr + 8)*SDIM + col] =
            make_float2(acc[nt][2], acc[nt][3]);
    }
}

// ---------------- rel-pos GEMM v2: chunked, natural-layout B ----------------
__global__ void __launch_bounds__(256) relgemm_kernel(const float* __restrict__ Er) {
    extern __shared__ float sm[];
    const int tid = threadIdx.x;
    const int h = blockIdx.y, b = blockIdx.z;

    if (blockIdx.x == NCHUNK) {   // fused V-mean for (b,h)
        const int bh = b*HEADS_N + h;
        const int d = tid & 63, sub = tid >> 6;
        float a = 0.f;
        for (int l = sub; l < TLEN; l += 4)
            a += g_v[((size_t)bh*TLEN + l)*SDIM + d];
        sm[sub*64 + d] = a;
        __syncthreads();
        if (sub == 0)
            g_vmean[bh*SDIM + d] =
                (sm[d] + sm[64 + d] + sm[128 + d] + sm[192 + d]) * (1.f/(float)TLEN);
        return;
    }

    float* Qh = sm;              // [m=64][k] stride 68
    float* Ql = Qh + 64*68;
    float* Eh = Ql + 64*68;      // [n=o][k=s] natural rows, stride 68
    float* El = Eh + 64*68;

    const int x = (int)blockIdx.x;
    int it = 31, cb = 0;
    {
        int base = 0;
        for (int k = 0; k < 32; k++) {
            int nch = (k + 4) >> 2;
            if (x < base + nch) { it = k; cb = base; break; }
            base += nch;
        }
    }
    const int chunk = x - cb;
    const int osta = chunk*4;
    const int oend = min(osta + 4, it + 1);
    const int i0 = it * 64;

    const float* gq = g_q + (size_t)(b*HEADS_N + h)*TLEN*SDIM + (size_t)i0*SDIM;
    const float* ge = Er + (size_t)h*TLEN*SDIM;

    #pragma unroll
    for (int kk = 0; kk < 4; kk++) {
        int k = kk*256 + tid;
        int m = k >> 4, s4 = (k & 15)*4;
        float4 f = *(const float4*)&gq[m*SDIM + s4];
        float hx = tf32r(f.x), hy = tf32r(f.y), hz = tf32r(f.z), hw = tf32r(f.w);
        *(float4*)&Qh[m*68 + s4] = make_float4(hx, hy, hz, hw);
        *(float4*)&Ql[m*68 + s4] = make_float4(
            tf32r(f.x - hx), tf32r(f.y - hy), tf32r(f.z - hz), tf32r(f.w - hw));
    }

    const int w = tid >> 5, lane = tid & 31;
    const int g = lane >> 2, tg = lane & 3;
    const int mr = (w & 3)*16 + g;
    const int nb = (w >> 2)*32;

    const int W = 64*(it + 1);
    float* qb = g_qe + (size_t)(b*HEADS_N + h)*QE_BH + (size_t)4096*(it*(it + 1)/2);

    for (int oc = osta; oc < oend; oc++) {
        const int j0 = TLEN - 64 - i0 + oc*64;
        __syncthreads();
        #pragma unroll
        for (int kk = 0; kk < 4; kk++) {
            int k = kk*256 + tid;
            int o = k >> 4, s4 = (k & 15)*4;
            float4 f = *(const float4*)&ge[(size_t)(j0 + o)*SDIM + s4];
            float hx = tf32r(f.x), hy = tf32r(f.y), hz = tf32r(f.z), hw = tf32r(f.w);
            *(float4*)&Eh[o*68 + s4] = make_float4(hx, hy, hz, hw);
            *(float4*)&El[o*68 + s4] = make_float4(
                tf32r(f.x - hx), tf32r(f.y - hy), tf32r(f.z - hz), tf32r(f.w - hw));
        }
        __syncthreads();

        float d[4][4];
        #pragma unroll
        for (int nt = 0; nt < 4; nt++)
            #pragma unroll
            for (int i = 0; i < 4; i++) d[nt][i] = 0.f;

        #pragma unroll
        for (int kk = 0; kk < 8; kk++) {
            const int k0 = kk*8;
            unsigned int ah0 = __float_as_uint(Qh[mr*68 + k0 + tg]);
            unsigned int ah1 = __float_as_uint(Qh[(mr + 8)*68 + k0 + tg]);
            unsigned int ah2 = __float_as_uint(Qh[mr*68 + k0 + tg + 4]);
            unsigned int ah3 = __float_as_uint(Qh[(mr + 8)*68 + k0 + tg + 4]);
            unsigned int al0 = __float_as_uint(Ql[mr*68 + k0 + tg]);
            unsigned int al1 = __float_as_uint(Ql[(mr + 8)*68 + k0 + tg]);
            unsigned int al2 = __float_as_uint(Ql[mr*68 + k0 + tg + 4]);
            unsigned int al3 = __float_as_uint(Ql[(mr + 8)*68 + k0 + tg + 4]);
            #pragma unroll
            for (int nt = 0; nt < 4; nt++) {
                const int n = nb + nt*8 + g;
                unsigned int bh0 = __float_as_uint(Eh[n*68 + k0 + tg]);
                unsigned int bh1 = __float_as_uint(Eh[n*68 + k0 + tg + 4]);
                unsigned int bl0 = __float_as_uint(El[n*68 + k0 + tg]);
                unsigned int bl1 = __float_as_uint(El[n*68 + k0 + tg + 4]);
                mma_tf32(d[nt], ah0, ah1, ah2, ah3, bh0, bh1);
                mma_tf32(d[nt], ah0, ah1, ah2, ah3, bl0, bl1);
                mma_tf32(d[nt], al0, al1, al2, al3, bh0, bh1);
            }
        }

        const int colb = oc*64 + nb;
        #pragma unroll
        for (int nt = 0; nt < 4; nt++) {
            const int col = colb + nt*8 + 2*tg;
            *(float2*)&qb[(size_t)mr*W + col]       = make_float2(d[nt][0], d[nt][1]);
            *(float2*)&qb[(size_t)(mr + 8)*W + col] = make_float2(d[nt][2], d[nt][3]);
        }
    }
}

// ---------------- split-KV tensor-core flash attention (partials) ---------------
// K and V staged ALREADY tf32-rounded (hi only). QK = (Qhi+Qlo)*Khi (2-term),
// PV = (Phi+Plo)*Vhi (2-term). Inner loops: pure LDS + bit-move + mma on B side.
#define AST 68   // 68 mod 32 == 4 -> all fragment LDS conflict-free
__global__ void __launch_bounds__(128, 3) attn_part_kernel() {
    extern __shared__ float sm[];
    float* sQ = sm;              // [i][s]  64 x AST  fp32
    float* sK = sQ + 64*AST;     // [c][s]  tf32-hi (pre-scaled)
    float* sV = sK + 64*AST;     // [lc][d] tf32-hi
    float* sP = sV + 64*AST;     // [i][lc] fp32

    const int x = NCHUNK - 1 - (int)blockIdx.x;   // heavy i-tiles first
    int it = 31, cb = 0;
    {
        int base = 0;
        for (int k = 0; k < 32; k++) {
            int nch = (k + 4) >> 2;
            if (x < base + nch) { it = k; cb = base; break; }
            base += nch;
        }
    }
    const int chunk = x - cb;
    const int csta = chunk*4;
    const int cend = min(csta + 4, it + 1);
    const int i0 = it * 64;

    const int h  = blockIdx.y;
    const int b  = blockIdx.z;
    const int tid = threadIdx.x;
    const int w = tid >> 5, lane = tid & 31;
    const int g = lane >> 2, tg = lane & 3;
    const int rA = w*16 + g, rB = rA + 8;
    const float scale2 = 0.04419417382415922f;   // 512^-0.5

    const size_t bh = (size_t)(b*HEADS_N + h);
    const float* gq = g_q + bh*TLEN*SDIM;
    const float* gk = g_k + bh*TLEN*SDIM;
    const float* gv = g_v + bh*TLEN*SDIM;

    const int Wqe = 64*(it + 1);
    const float* qeb = g_qe + bh*QE_BH + (size_t)4096*(it*(it + 1)/2);
    const int omax = i0 + 63;

    for (int k = tid; k < 1024; k += 128) {
        int li = k >> 4, s4 = (k & 15)*4;
        *(float4*)&sQ[li*AST + s4] =
            *(const float4*)&gq[(size_t)(i0 + li)*SDIM + s4];
    }

    float mA = -1e30f, mB = -1e30f, lA = 0.f, lB = 0.f;
    float O[8][4];
    #pragma unroll
    for (int nt = 0; nt < 8; nt++)
        #pragma unroll
        for (int i = 0; i < 4; i++) O[nt][i] = 0.f;

    for (int ct = csta; ct < cend; ct++) {
        const int c0 = ct * 64;
        __syncthreads();
        for (int k = tid; k < 1024; k += 128) {
            int li = k >> 4, s4 = (k & 15)*4;
            float4 f = *(const float4*)&gk[(size_t)(c0 + li)*SDIM + s4];
            *(float4*)&sK[li*AST + s4] = make_float4(
                tf32r(f.x*scale2), tf32r(f.y*scale2),
                tf32r(f.z*scale2), tf32r(f.w*scale2));
            float4 v = *(const float4*)&gv[(size_t)(c0 + li)*SDIM + s4];
            *(float4*)&sV[li*AST + s4] = make_float4(
                tf32r(v.x), tf32r(v.y), tf32r(v.z), tf32r(v.w));
        }
        __syncthreads();

        float acc[8][4];
        #pragma unroll
        for (int nt = 0; nt < 8; nt++)
            #pragma unroll
            for (int i = 0; i < 4; i++) acc[nt][i] = 0.f;

        // ---- S = Q K^T : (Qhi + Qlo) * Khi, K pre-rounded ----
        #pragma unroll
        for (int kk = 0; kk < 8; kk++) {
            const int k0 = kk*8;
            float q0 = sQ[rA*AST + k0 + tg];
            float q1 = sQ[rB*AST + k0 + tg];
            float q2 = sQ[rA*AST + k0 + tg + 4];
            float q3 = sQ[rB*AST + k0 + tg + 4];
            unsigned int ah0 = f2tf32(q0), ah1 = f2tf32(q1);
            unsigned int ah2 = f2tf32(q2), ah3 = f2tf32(q3);
            unsigned int al0 = f2tf32(q0 - __uint_as_float(ah0));
            unsigned int al1 = f2tf32(q1 - __uint_as_float(ah1));
            unsigned int al2 = f2tf32(q2 - __uint_as_float(ah2));
            unsigned int al3 = f2tf32(q3 - __uint_as_float(ah3));
            #pragma unroll
            for (int nt = 0; nt < 8; nt++) {
                const int n = nt*8 + g;
                unsigned int bh0 = __float_as_uint(sK[n*AST + k0 + tg]);
                unsigned int bh1 = __float_as_uint(sK[n*AST + k0 + tg + 4]);
                mma_tf32(acc[nt], ah0, ah1, ah2, ah3, bh0, bh1);
                mma_tf32(acc[nt], al0, al1, al2, al3, bh0, bh1);
            }
        }

        #pragma unroll
        for (int nt = 0; nt < 8; nt++) {
            const int cl = nt*8 + 2*tg;
            const int oA = 63 - rA + c0 + cl;
            const int oB = 63 - rB + c0 + cl;
            if (oA     <= omax) acc[nt][0] += __ldg(qeb + (size_t)rA*Wqe + oA);
            if (oA + 1 <= omax) acc[nt][1] += __ldg(qeb + (size_t)rA*Wqe + oA + 1);
            if (oB     <= omax) acc[nt][2] += __ldg(qeb + (size_t)rB*Wqe + oB);
            if (oB + 1 <= omax) acc[nt][3] += __ldg(qeb + (size_t)rB*Wqe + oB + 1);
            if (ct == it) {
                if (cl     > rA) acc[nt][0] = -1e30f;
                if (cl + 1 > rA) acc[nt][1] = -1e30f;
                if (cl     > rB) acc[nt][2] = -1e30f;
                if (cl + 1 > rB) acc[nt][3] = -1e30f;
            }
        }

        float mxA = -1e30f, mxB = -1e30f;
        #pragma unroll
        for (int nt = 0; nt < 8; nt++) {
            mxA = fmaxf(mxA, fmaxf(acc[nt][0], acc[nt][1]));
            mxB = fmaxf(mxB, fmaxf(acc[nt][2], acc[nt][3]));
        }
        mxA = fmaxf(mxA, __shfl_xor_sync(0xffffffffu, mxA, 1));
        mxA = fmaxf(mxA, __shfl_xor_sync(0xffffffffu, mxA, 2));
        mxB = fmaxf(mxB, __shfl_xor_sync(0xffffffffu, mxB, 1));
        mxB = fmaxf(mxB, __shfl_xor_sync(0xffffffffu, mxB, 2));
        const float mnA = fmaxf(mA, mxA), mnB = fmaxf(mB, mxB);
        const float cA = __expf(mA - mnA), cB = __expf(mB - mnB);
        float sA = 0.f, sB = 0.f;
        #pragma unroll
        for (int nt = 0; nt < 8; nt++) {
            acc[nt][0] = __expf(acc[nt][0] - mnA);
            acc[nt][1] = __expf(acc[nt][1] - mnA);
            acc[nt][2] = __expf(acc[nt][2] - mnB);
            acc[nt][3] = __expf(acc[nt][3] - mnB);
            sA += acc[nt][0] + acc[nt][1];
            sB += acc[nt][2] + acc[nt][3];
        }
        sA += __shfl_xor_sync(0xffffffffu, sA, 1);
        sA += __shfl_xor_sync(0xffffffffu, sA, 2);
        sB += __shfl_xor_sync(0xffffffffu, sB, 1);
        sB += __shfl_xor_sync(0xffffffffu, sB, 2);
        lA = lA*cA + sA;  mA = mnA;
        lB = lB*cB + sB;  mB = mnB;
        #pragma unroll
        for (int nt = 0; nt < 8; nt++) {
            O[nt][0] *= cA; O[nt][1] *= cA;
            O[nt][2] *= cB; O[nt][3] *= cB;
        }

        #pragma unroll
        for (int nt = 0; nt < 8; nt++) {
            *(float2*)&sP[rA*AST + nt*8 + 2*tg] = make_float2(acc[nt][0], acc[nt][1]);
            *(float2*)&sP[rB*AST + nt*8 + 2*tg] = make_float2(acc[nt][2], acc[nt][3]);
        }
        __syncwarp();

        // ---- O += P V : (Phi + Plo) * Vhi, V pre-rounded ----
        #pragma unroll
        for (int kk = 0; kk < 8; kk++) {
            const int k0 = kk*8;
            float p0 = sP[rA*AST + k0 + tg];
            float p1 = sP[rB*AST + k0 + tg];
            float p2 = sP[rA*AST + k0 + tg + 4];
            float p3 = sP[rB*AST + k0 + tg + 4];
            unsigned int ah0 = f2tf32(p0), ah1 = f2tf32(p1);
            unsigned int ah2 = f2tf32(p2), ah3 = f2tf32(p3);
            unsigned int al0 = f2tf32(p0 - __uint_as_float(ah0));
            unsigned int al1 = f2tf32(p1 - __uint_as_float(ah1));
            unsigned int al2 = f2tf32(p2 - __uint_as_float(ah2));
            unsigned int al3 = f2tf32(p3 - __uint_as_float(ah3));
            #pragma unroll
            for (int nt = 0; nt < 8; nt++) {
                const int n = nt*8 + g;
                unsigned int bh0 = __float_as_uint(sV[(k0 + tg)*AST + n]);
                unsigned int bh1 = __float_as_uint(sV[(k0 + tg + 4)*AST + n]);
                mma_tf32(O[nt], ah0, ah1, ah2, ah3, bh0, bh1);
                mma_tf32(O[nt], al0, al1, al2, al3, bh0, bh1);
            }
        }
    }

    const int slot = (int)(bh*NCHUNK) + cb + chunk;
    float* pO = g_pO + (size_t)slot*64*64;
    #pragma unroll
    for (int nt = 0; nt < 8; nt++) {
        *(float2*)&pO[rA*64 + nt*8 + 2*tg] = make_float2(O[nt][0], O[nt][1]);
        *(float2*)&pO[rB*64 + nt*8 + 2*tg] = make_float2(O[nt][2], O[nt][3]);
    }
    if (tg == 0) {
        g_pm[slot*64 + rA] = mA;  g_pl[slot*64 + rA] = lA;
        g_pm[slot*64 + rB] = mB;  g_pl[slot*64 + rB] = lB;
    }
}

// ---------------- split-KV reduce: merge partials, mask, scramble --------------
__global__ void __launch_bounds__(128) reduce_kernel() {
    const int it = blockIdx.x, h = blockIdx.y, b = blockIdx.z;
    int base = 0;
    for (int k = 0; k < it; k++) base += (k + 4) >> 2;
    const int nc = (it + 4) >> 2;
    const int slot0 = (b*HEADS_N + h)*NCHUNK + base;
    const int tid = threadIdx.x;
    const int row = tid >> 1;
    const int half = (tid & 1)*32;

    float mstar = -1e30f;
    for (int p = 0; p < nc; p++)
        mstar = fmaxf(mstar, g_pm[(slot0 + p)*64 + row]);

    float lstar = 0.f;
    float Oa[32];
    #pragma unroll
    for (int d = 0; d < 32; d++) Oa[d] = 0.f;

    for (int p = 0; p < nc; p++) {
        const float f = __expf(g_pm[(slot0 + p)*64 + row] - mstar);
        lstar += g_pl[(slot0 + p)*64 + row] * f;
        const float* po = g_pO + ((size_t)(slot0 + p)*64 + row)*64 + half;
        #pragma unroll
        for (int d4 = 0; d4 < 8; d4++) {
            float4 v = *(const float4*)&po[d4*4];
            Oa[d4*4 + 0] += f*v.x;
            Oa[d4*4 + 1] += f*v.y;
            Oa[d4*4 + 2] += f*v.z;
            Oa[d4*4 + 3] += f*v.w;
        }
    }

    const int i = it*64 + row;
    const unsigned int mk = g_pmask[b*TLEN + i];
    const float inv = 1.f / lstar;
    float* dst = &g_attn[((size_t)(b*TLEN) + h*256 + (i >> 3))*EDIM
                         + ((i & 7) << 6) + half];
    if (mk != 0u) {
        #pragma unroll
        for (int d = 0; d < 32; d++) dst[d] = Oa[d]*inv;
    } else {
        const float* vm = &g_vmean[(b*HEADS_N + h)*SDIM + half];
        #pragma unroll
        for (int d = 0; d < 32; d++) dst[d] = vm[d];
    }
}

// ---------------- output projection via tf32 3x mma ----------------------------
__global__ void __launch_bounds__(256) outproj_kernel(const float* __restrict__ Wo,
                                                      const float* __restrict__ bo,
                                                      float* __restrict__ out) {
    extern __shared__ float sm[];
    float* sA  = sm;             // [row=128][k=64] fp32, stride 68
    float* sBh = sA + 128*68;    // [n=64][k] hi
    float* sBl = sBh + 64*68;    // lo

    const int m0 = blockIdx.x * 128;
    const int n0 = blockIdx.y * 64;
    const int tid = threadIdx.x;
    const int w = tid >> 5, lane = tid & 31;
    const int g = lane >> 2, tg = lane & 3;
    const int mr = w*16 + g;

    float acc[8][4];
    #pragma unroll
    for (int nt = 0; nt < 8; nt++)
        #pragma unroll
        for (int i = 0; i < 4; i++) acc[nt][i] = 0.f;

    for (int ks = 0; ks < 8; ks++) {
        const int kc = ks*64;
        __syncthreads();
        for (int k = tid; k < 2048; k += 256) {
            int row = k >> 4, i4 = (k & 15)*4;
            *(float4*)&sA[row*68 + i4] =
                *(const float4*)&g_attn[(size_t)(m0 + row)*EDIM + kc + i4];
        }
        for (int k = tid; k < 1024; k += 256) {
            int row = k >> 4, i4 = (k & 15)*4;
            float4 f = *(const float4*)&Wo[(size_t)(n0 + row)*EDIM + kc + i4];
            float hx = tf32r(f.x), hy = tf32r(f.y), hz = tf32r(f.z), hw = tf32r(f.w);
            *(float4*)&sBh[row*68 + i4] = make_float4(hx, hy, hz, hw);
            *(float4*)&sBl[row*68 + i4] = make_float4(
                tf32r(f.x - hx), tf32r(f.y - hy), tf32r(f.z - hz), tf32r(f.w - hw));
        }
        __syncthreads();

        #pragma unroll
        for (int kk = 0; kk < 8; kk++) {
            const int k0 = kk*8;
            float q0 = sA[mr*68 + k0 + tg];
            float q1 = sA[(mr + 8)*68 + k0 + tg];
            float q2 = sA[mr*68 + k0 + tg + 4];
            float q3 = sA[(mr + 8)*68 + k0 + tg + 4];
            unsigned int ah0 = f2tf32(q0), ah1 = f2tf32(q1);
            unsigned int ah2 = f2tf32(q2), ah3 = f2tf32(q3);
            unsigned int al0 = f2tf32(q0 - __uint_as_float(ah0));
            unsigned int al1 = f2tf32(q1 - __uint_as_float(ah1));
            unsigned int al2 = f2tf32(q2 - __uint_as_float(ah2));
            unsigned int al3 = f2tf32(q3 - __uint_as_float(ah3));
            #pragma unroll
            for (int nt = 0; nt < 8; nt++) {
                const int n = nt*8 + g;
                unsigned int bh0 = __float_as_uint(sBh[n*68 + k0 + tg]);
                unsigned int bh1 = __float_as_uint(sBh[n*68 + k0 + tg + 4]);
                unsigned int bl0 = __float_as_uint(sBl[n*68 + k0 + tg]);
                unsigned int bl1 = __float_as_uint(sBl[n*68 + k0 + tg + 4]);
                mma_tf32(acc[nt], ah0, ah1, ah2, ah3, bh0, bh1);
                mma_tf32(acc[nt], ah0, ah1, ah2, ah3, bl0, bl1);
                mma_tf32(acc[nt], al0, al1, al2, al3, bh0, bh1);
            }
        }
    }

    #pragma unroll
    for (int nt = 0; nt < 8; nt++) {
        const int col = n0 + nt*8 + 2*tg;
        const float b0v = bo[col], b1v = bo[col + 1];
        *(float2*)&out[(size_t)(m0 + mr)*EDIM + col] =
            make_float2(acc[nt][0] + b0v, acc[nt][1] + b1v);
        *(float2*)&out[(size_t)(m0 + mr + 8)*EDIM + col] =
            make_float2(acc[nt][2] + b0v, acc[nt][3] + b1v);
    }
}

// ---------------- launch ----------------
extern "C" void kernel_launch(void* const* d_in, const int* in_sizes, int n_in,
                              void* d_out, int out_size) {
    int idx_x = -1, idx_Er = -1, idx_Wo = -1, idx_bo = -1;
    int cand[8]; int ncand = 0;
    for (int scale = 1; scale <= 4; scale *= 4) {
        idx_x = idx_Er = idx_Wo = idx_bo = -1; ncand = 0;
        for (int i = 0; i < n_in; i++) {
            long long s = in_sizes[i];
            if      (s == (long long)BATCH*TLEN*EDIM*scale)   idx_x  = i;
            else if (s == (long long)HEADS_N*TLEN*SDIM*scale) idx_Er = i;
            else if (s == (long long)EDIM*EDIM*scale)         idx_Wo = i;
            else if (s == (long long)EDIM*scale)              idx_bo = i;
            else if (s == (long long)SDIM*SDIM*scale && ncand < 8) cand[ncand++] = i;
        }
        if (idx_x >= 0 && idx_Er >= 0 && idx_Wo >= 0 && idx_bo >= 0 && ncand == 4)
            break;
    }
    if (!(idx_x >= 0 && idx_Er >= 0 && idx_Wo >= 0 && idx_bo >= 0 && ncand == 4)) {
        int wi = (n_in >= 9) ? 3 : 2;
        idx_x = 0; cand[0] = 1; cand[1] = wi; cand[2] = wi + 1; cand[3] = wi + 2;
        idx_Er = wi + 3; idx_Wo = wi + 4; idx_bo = wi + 5; ncand = 4;
    }

    const float* x  = (const float*)d_in[idx_x];
    const float* Er = (const float*)d_in[idx_Er];
    const float* Wo = (const float*)d_in[idx_Wo];
    const float* bo = (const float*)d_in[idx_bo];
    float* out = (float*)d_out;

    const int PROJ_SMEM = (256*68) * (int)sizeof(float);            // 69632 B
    const int ATTN_SMEM = (4*64*AST) * (int)sizeof(float);          // 69632 B
    const int RG_SMEM   = (4*64*68) * (int)sizeof(float);           // 69632 B
    const int OP_SMEM   = (256*68) * (int)sizeof(float);            // 69632 B
    cudaFuncSetAttribute(proj_kernel, cudaFuncAttributeMaxDynamicSharedMemorySize, PROJ_SMEM);
    cudaFuncSetAttribute(attn_part_kernel, cudaFuncAttributeMaxDynamicSharedMemorySize, ATTN_SMEM);
    cudaFuncSetAttribute(relgemm_kernel, cudaFuncAttributeMaxDynamicSharedMemorySize, RG_SMEM);
    cudaFuncSetAttribute(outproj_kernel, cudaFuncAttributeMaxDynamicSharedMemorySize, OP_SMEM);

    select_inputs<<<1, 256>>>((const float*)d_in[cand[0]], (const float*)d_in[cand[1]],
                              (const float*)d_in[cand[2]], (const float*)d_in[cand[3]],
                              (idx_x == 0) ? 1 : 0);
    proj_kernel<<<dim3(TLEN/128, 3*HEADS_N, BATCH), 256, PROJ_SMEM>>>(x);
    relgemm_kernel<<<dim3(NCHUNK + 1, HEADS_N, BATCH), 256, RG_SMEM>>>(Er);
    attn_part_kernel<<<dim3(NCHUNK, HEADS_N, BATCH), 128, ATTN_SMEM>>>();
    reduce_kernel<<<dim3(TLEN/64, HEADS_N, BATCH), 128>>>();
    outproj_kernel<<<dim3((BATCH*TLEN)/128, EDIM/64), 256, OP_SMEM>>>(Wo, bo, out);
}